// round 10
// baseline (speedup 1.0000x reference)
#include <cuda_runtime.h>
#include <cuda_fp16.h>
#include <math.h>
#include <stdint.h>

// ---------------- problem constants ----------------
#define BATCH 4
#define SEQ   2048
#define DIM   1024
#define NH    8
#define HD    128
#define WIN   16
#define EPSV  1e-6f
#define MR    (BATCH*SEQ)   // 8192
#define NQKV  3072
#define NW    4096          // transposed weight rows: 3072 qkv + 1024 wo

// ---------------- device scratch ----------------
__device__ __align__(16) __half g_wT[NW*DIM];     // fp16 transposed weights [n][k]
__device__ __align__(16) __half g_xh[MR*DIM];
__device__ __align__(16) float  g_qkv[MR*NQKV];
__device__ __align__(16) __half g_yh[MR*DIM];
__device__ __align__(16) float  g_rsq[MR];
__device__ __align__(16) float  g_rsk[MR];

// ---------------- PTX helpers ----------------
__device__ __forceinline__ uint32_t smem_u32(const void* p) {
    uint32_t a;
    asm("{ .reg .u64 t; cvta.to.shared.u64 t, %1; cvt.u32.u64 %0, t; }" : "=r"(a) : "l"(p));
    return a;
}
__device__ __forceinline__ void cp16(uint32_t d, const void* s) {
    asm volatile("cp.async.cg.shared.global [%0], [%1], 16;" :: "r"(d), "l"(s));
}
__device__ __forceinline__ void cp_commit() { asm volatile("cp.async.commit_group;" ::: "memory"); }
__device__ __forceinline__ void cp_wait1()  { asm volatile("cp.async.wait_group 1;" ::: "memory"); }
__device__ __forceinline__ void cp_wait0()  { asm volatile("cp.async.wait_group 0;" ::: "memory"); }

__device__ __forceinline__ void ldm_x4(uint32_t* r, uint32_t addr) {
    asm volatile("ldmatrix.sync.aligned.m8n8.x4.shared.b16 {%0,%1,%2,%3}, [%4];"
                 : "=r"(r[0]), "=r"(r[1]), "=r"(r[2]), "=r"(r[3]) : "r"(addr));
}
__device__ __forceinline__ void mma_f16(float* c, const uint32_t* a, const uint32_t* b) {
    asm volatile(
        "mma.sync.aligned.m16n8k16.row.col.f32.f16.f16.f32 "
        "{%0,%1,%2,%3}, {%4,%5,%6,%7}, {%8,%9}, {%0,%1,%2,%3};"
        : "+f"(c[0]), "+f"(c[1]), "+f"(c[2]), "+f"(c[3])
        : "r"(a[0]), "r"(a[1]), "r"(a[2]), "r"(a[3]), "r"(b[0]), "r"(b[1]));
}

// ---------------- transpose all 4 weights -> g_wT fp16 [n][k] ----------------
__global__ __launch_bounds__(256)
void transpose_all(const float* __restrict__ wq, const float* __restrict__ wk,
                   const float* __restrict__ wv, const float* __restrict__ wo,
                   __half* __restrict__ wT)
{
    __shared__ float t[32][33];
    const float* W = (blockIdx.z == 0) ? wq : (blockIdx.z == 1) ? wk
                    : (blockIdx.z == 2) ? wv : wo;
    __half* out = wT + (size_t)blockIdx.z * DIM * DIM;
    const int c0 = blockIdx.x * 32, r0 = blockIdx.y * 32;
    const int tx = threadIdx.x, ty = threadIdx.y;
#pragma unroll
    for (int j = 0; j < 4; j++)
        t[ty + 8*j][tx] = W[(size_t)(r0 + ty + 8*j) * DIM + c0 + tx];
    __syncthreads();
#pragma unroll
    for (int j = 0; j < 4; j++)
        out[(size_t)(c0 + ty + 8*j) * DIM + (r0 + tx)] = __float2half_rn(t[tx][ty + 8*j]);
}

// ---------------- fp32 -> fp16 convert ----------------
__global__ __launch_bounds__(256)
void cvt16(const float* __restrict__ x, __half* __restrict__ hi, int n4)
{
    int i = blockIdx.x * 256 + threadIdx.x;
    if (i >= n4) return;
    float4 v = ((const float4*)x)[i];
    __half2 H0; H0.x = __float2half_rn(v.x); H0.y = __float2half_rn(v.y);
    __half2 H1; H1.x = __float2half_rn(v.z); H1.y = __float2half_rn(v.w);
    ((__half2*)hi)[2*i]   = H0;
    ((__half2*)hi)[2*i+1] = H1;
}

// ---------------- fp16 warp-MMA GEMM: C = A @ B^T ----------------
// CTA 128x128, BK=64 fp16 (128B rows, full SW128 swizzle), 3-stage cp.async,
// 8 warps of 32x64, 2 CTAs/SM.
#define TILEB  16384             // 128 rows x 128 bytes
#define STAGEB (2*TILEB)         // A, B
#define GSMEM  (3*STAGEB)        // 98304

__device__ __forceinline__ uint32_t swz(uint32_t tile, int row, int chunk) {
    return tile + row * 128 + (((uint32_t)(chunk ^ (row & 7))) << 4);
}
__device__ __forceinline__ void ld_tile(uint32_t sdst, const __half* g,
                                        int grow0, int k0, int lrow, int lc0)
{
    const __half* src = g + (size_t)(grow0 + lrow) * DIM + k0;
#pragma unroll
    for (int c = 0; c < 4; c++)
        cp16(swz(sdst, lrow, lc0 + c), src + (lc0 + c) * 8);
}

__global__ __launch_bounds__(256, 2)
void gemm_f16(const __half* __restrict__ a, const __half* __restrict__ b,
              float* __restrict__ C, int ldc)
{
    extern __shared__ char smem[];
    const uint32_t sbase = smem_u32(smem);
    const int tid  = threadIdx.x;
    const int lane = tid & 31;
    const int wid  = tid >> 5;
    const int wm   = wid >> 1;          // 0..3 -> 32-row strip
    const int wn   = wid & 1;           // 0..1 -> 64-col strip
    const int m0 = blockIdx.y * 128;
    const int n0 = blockIdx.x * 128;

    const int lrow = tid >> 1;          // 0..127
    const int lc0  = (tid & 1) * 4;     // 0 or 4

    // fragment addressing
    int arow[2], browx[4];
#pragma unroll
    for (int mt = 0; mt < 2; mt++) arow[mt] = wm * 32 + mt * 16 + (lane & 15);
#pragma unroll
    for (int p = 0; p < 4; p++)
        browx[p] = wn * 64 + p * 16 + ((lane >> 4) << 3) + (lane & 7);
    const int ac = lane >> 4;           // A chunk selector
    const int bc = (lane >> 3) & 1;     // B chunk selector

    float acc[2][8][4];
#pragma unroll
    for (int mt = 0; mt < 2; mt++)
#pragma unroll
        for (int nt = 0; nt < 8; nt++)
#pragma unroll
            for (int q = 0; q < 4; q++) acc[mt][nt][q] = 0.0f;

#pragma unroll
    for (int s = 0; s < 2; s++) {
        const uint32_t st = sbase + s * STAGEB;
        const int k0 = s * 64;
        ld_tile(st,         a, m0, k0, lrow, lc0);
        ld_tile(st + TILEB, b, n0, k0, lrow, lc0);
        cp_commit();
    }

    const int NIT = DIM / 64;           // 16
    for (int i = 0; i < NIT; i++) {
        if (i < NIT - 1) cp_wait1(); else cp_wait0();
        __syncthreads();

        if (i + 2 < NIT) {
            const uint32_t st = sbase + ((i + 2) % 3) * STAGEB;
            const int k0 = (i + 2) * 64;
            ld_tile(st,         a, m0, k0, lrow, lc0);
            ld_tile(st + TILEB, b, n0, k0, lrow, lc0);
            cp_commit();
        }

        const uint32_t st = sbase + (i % 3) * STAGEB;
        const uint32_t sA = st;
        const uint32_t sB = st + TILEB;

#pragma unroll
        for (int kh = 0; kh < 4; kh++) {
            uint32_t fB[4][4], fA[2][4];
#pragma unroll
            for (int p = 0; p < 4; p++)
                ldm_x4(fB[p], swz(sB, browx[p], kh * 2 + bc));
#pragma unroll
            for (int mt = 0; mt < 2; mt++)
                ldm_x4(fA[mt], swz(sA, arow[mt], kh * 2 + ac));
#pragma unroll
            for (int mt = 0; mt < 2; mt++)
#pragma unroll
                for (int p = 0; p < 4; p++) {
                    mma_f16(acc[mt][p*2],     fA[mt], &fB[p][0]);
                    mma_f16(acc[mt][p*2 + 1], fA[mt], &fB[p][2]);
                }
        }
    }

    const int erow = lane >> 2;
    const int ecol = (lane & 3) * 2;
#pragma unroll
    for (int mt = 0; mt < 2; mt++) {
#pragma unroll
        for (int nt = 0; nt < 8; nt++) {
            const int r0 = m0 + wm * 32 + mt * 16 + erow;
            const int c0 = n0 + wn * 64 + nt * 8 + ecol;
            float2 v0 = {acc[mt][nt][0], acc[mt][nt][1]};
            float2 v1 = {acc[mt][nt][2], acc[mt][nt][3]};
            *(float2*)(C + (size_t)r0 * ldc + c0)       = v0;
            *(float2*)(C + (size_t)(r0 + 8) * ldc + c0) = v1;
        }
    }
}

// ---------------- per-row rsqrt factors for q/k slices (read-only pass) ----------------
__global__ __launch_bounds__(256)
void normfact_kernel(const float* __restrict__ qkv, float* __restrict__ rsq,
                     float* __restrict__ rsk)
{
    const int row = blockIdx.x;
    const int tid = threadIdx.x;
    const float* xr = qkv + (size_t)row * NQKV + blockIdx.y * DIM;

    float4 v = *(const float4*)(xr + tid * 4);
    float ss = v.x*v.x + v.y*v.y + v.z*v.z + v.w*v.w;

    __shared__ float red[8];
#pragma unroll
    for (int o = 16; o; o >>= 1) ss += __shfl_xor_sync(0xFFFFFFFFu, ss, o);
    if ((tid & 31) == 0) red[tid >> 5] = ss;
    __syncthreads();
    if (tid < 32) {
        float s = (tid < 8) ? red[tid] : 0.0f;
#pragma unroll
        for (int o = 4; o; o >>= 1) s += __shfl_xor_sync(0xFFFFFFFFu, s, o);
        if (tid == 0) {
            float rs = rsqrtf(s * (1.0f / DIM) + EPSV);
            (blockIdx.y == 0 ? rsq : rsk)[row] = rs;
        }
    }
}

// ---------------- banded attention with fused norm; fp16 out ----------------
#define ASMEM (2 * 80 * 132 * 4)

__global__ __launch_bounds__(256)
void attn_kernel(const float* __restrict__ qkv, const float* __restrict__ rsq,
                 const float* __restrict__ rsk, const float* __restrict__ qnw,
                 const float* __restrict__ knw, __half* __restrict__ yh)
{
    extern __shared__ float sm[];
    float* ks = sm;
    float* vs = sm + 80 * 132;
    const int tid  = threadIdx.x;
    const int lane = tid & 31;
    const int wid  = tid >> 5;
    const int qb = blockIdx.x * 64;
    const int h  = blockIdx.y;
    const int b  = blockIdx.z;

    const float* kbase = qkv + (size_t)(b * SEQ) * NQKV + DIM     + h * HD;
    const float* vbase = qkv + (size_t)(b * SEQ) * NQKV + 2 * DIM + h * HD;
    const float4* kw4p = (const float4*)(knw + h * HD);

    // stage k (normed) and v
    for (int idx = tid; idx < 80 * 32; idx += 256) {
        const int r = idx >> 5, c = idx & 31;
        const int gr = qb - WIN + r;
        if (gr >= 0) {
            const float f = rsk[b * SEQ + gr];
            float4 kv = ((const float4*)(kbase + (size_t)gr * NQKV))[c];
            float4 w4 = kw4p[c];
            kv.x *= f * w4.x; kv.y *= f * w4.y; kv.z *= f * w4.z; kv.w *= f * w4.w;
            ((float4*)(ks + r * 132))[c] = kv;
            ((float4*)(vs + r * 132))[c] = ((const float4*)(vbase + (size_t)gr * NQKV))[c];
        }
    }
    __syncthreads();

    const float scale = 0.08838834764831845f;   // 1/sqrt(128)
    const float slope = exp2f(-(float)h);       // ALiBi slope, H=8
    const float4 qw4 = ((const float4*)(qnw + h * HD))[lane];

#pragma unroll 1
    for (int it = 0; it < 8; it++) {
        const int t = qb + it * 8 + wid;
        float4 q = *(const float4*)(qkv + (size_t)(b * SEQ + t) * NQKV + h * HD + lane * 4);
        const float qf = rsq[b * SEQ + t] * scale;
        q.x *= qf * qw4.x; q.y *= qf * qw4.y; q.z *= qf * qw4.z; q.w *= qf * qw4.w;

        float sc[WIN + 1];
        float mx = -1e30f;
#pragma unroll
        for (int jj = 0; jj <= WIN; jj++) {
            const int j = t - WIN + jj;
            float s = -1e30f;
            if (j >= 0) {
                const int sr = j - qb + WIN;
                const float4 k4 = *(const float4*)(ks + sr * 132 + lane * 4);
                float d = q.x*k4.x + q.y*k4.y + q.z*k4.z + q.w*k4.w;
#pragma unroll
                for (int o = 16; o; o >>= 1) d += __shfl_xor_sync(0xFFFFFFFFu, d, o);
                s = d + slope * (float)(j - t);
            }
            sc[jj] = s;
            mx = fmaxf(mx, s);
        }
        float l = 0.0f;
#pragma unroll
        for (int jj = 0; jj <= WIN; jj++) {
            float e = __expf(sc[jj] - mx);
            sc[jj] = e;
            l += e;
        }
        const float inv = 1.0f / l;

        float4 acc = {0.f, 0.f, 0.f, 0.f};
#pragma unroll
        for (int jj = 0; jj <= WIN; jj++) {
            const int j = t - WIN + jj;
            if (j >= 0) {
                const int sr = j - qb + WIN;
                const float4 v4 = *(const float4*)(vs + sr * 132 + lane * 4);
                const float p = sc[jj] * inv;
                acc.x = fmaf(p, v4.x, acc.x);
                acc.y = fmaf(p, v4.y, acc.y);
                acc.z = fmaf(p, v4.z, acc.z);
                acc.w = fmaf(p, v4.w, acc.w);
            }
        }

        const size_t off = (size_t)(b * SEQ + t) * DIM + h * HD + lane * 4;
        __half2 H0; H0.x = __float2half_rn(acc.x); H0.y = __float2half_rn(acc.y);
        __half2 H1; H1.x = __float2half_rn(acc.z); H1.y = __float2half_rn(acc.w);
        ((__half2*)(yh + off))[0] = H0;
        ((__half2*)(yh + off))[1] = H1;
    }
}

// ---------------- launch ----------------
extern "C" void kernel_launch(void* const* d_in, const int* in_sizes, int n_in,
                              void* d_out, int out_size)
{
    const float* x   = (const float*)d_in[0];
    const float* wq  = (const float*)d_in[1];
    const float* wk  = (const float*)d_in[2];
    const float* wv  = (const float*)d_in[3];
    const float* wo  = (const float*)d_in[4];
    const float* qnw = (const float*)d_in[5];
    const float* knw = (const float*)d_in[6];
    float* out       = (float*)d_out;

    __half *wT, *xh, *yh;
    float *qkv, *rsq, *rsk;
    cudaGetSymbolAddress((void**)&wT,  g_wT);
    cudaGetSymbolAddress((void**)&xh,  g_xh);
    cudaGetSymbolAddress((void**)&qkv, g_qkv);
    cudaGetSymbolAddress((void**)&yh,  g_yh);
    cudaGetSymbolAddress((void**)&rsq, g_rsq);
    cudaGetSymbolAddress((void**)&rsk, g_rsk);

    cudaFuncSetAttribute(gemm_f16,    cudaFuncAttributeMaxDynamicSharedMemorySize, GSMEM);
    cudaFuncSetAttribute(attn_kernel, cudaFuncAttributeMaxDynamicSharedMemorySize, ASMEM);

    // 1) transpose all weights -> fp16 [n][k], rows: [wq|wk|wv|wo]
    dim3 tgrid(DIM/32, DIM/32, 4), tblk(32, 8);
    transpose_all<<<tgrid, tblk>>>(wq, wk, wv, wo, wT);

    // 2) convert x to fp16
    cvt16<<<(MR*DIM/4 + 255)/256, 256>>>(x, xh, MR*DIM/4);

    // 3) fused QKV projection: [8192x1024] @ [1024x3072]
    dim3 qkvgrid(NQKV/128, MR/128);
    gemm_f16<<<qkvgrid, 256, GSMEM>>>(xh, wT, qkv, NQKV);

    // 4) per-row norm factors (read-only)
    dim3 ngrid(MR, 2);
    normfact_kernel<<<ngrid, 256>>>(qkv, rsq, rsk);

    // 5) banded attention with fused norm -> y fp16
    dim3 agrid(SEQ/64, NH, BATCH);
    attn_kernel<<<agrid, 256, ASMEM>>>(qkv, rsq, rsk, qnw, knw, yh);

    // 6) output projection: [8192x1024] @ [1024x1024]
    dim3 ogrid(DIM/128, MR/128);
    gemm_f16<<<ogrid, 256, GSMEM>>>(yh, wT + (size_t)3072*DIM, out, DIM);
}

// round 11
// speedup vs baseline: 1.0223x; 1.0223x over previous
#include <cuda_runtime.h>
#include <cuda_fp16.h>
#include <math.h>
#include <stdint.h>

// ---------------- problem constants ----------------
#define BATCH 4
#define SEQ   2048
#define DIM   1024
#define NH    8
#define HD    128
#define WIN   16
#define EPSV  1e-6f
#define MR    (BATCH*SEQ)   // 8192
#define NQKV  3072
#define NW    4096          // transposed weight rows: 3072 qkv + 1024 wo

// ---------------- device scratch ----------------
__device__ __align__(16) __half g_wT[NW*DIM];     // fp16 transposed weights [n][k]
__device__ __align__(16) __half g_xh[MR*DIM];
__device__ __align__(16) float  g_qkv[MR*NQKV];
__device__ __align__(16) __half g_yh[MR*DIM];
__device__ __align__(16) float  g_rsq[MR];
__device__ __align__(16) float  g_rsk[MR];

// ---------------- PTX helpers ----------------
__device__ __forceinline__ uint32_t smem_u32(const void* p) {
    uint32_t a;
    asm("{ .reg .u64 t; cvta.to.shared.u64 t, %1; cvt.u32.u64 %0, t; }" : "=r"(a) : "l"(p));
    return a;
}
__device__ __forceinline__ void cp16(uint32_t d, const void* s) {
    asm volatile("cp.async.cg.shared.global [%0], [%1], 16;" :: "r"(d), "l"(s));
}
__device__ __forceinline__ void cp_commit() { asm volatile("cp.async.commit_group;" ::: "memory"); }
__device__ __forceinline__ void cp_wait1()  { asm volatile("cp.async.wait_group 1;" ::: "memory"); }

__device__ __forceinline__ void ldm_x4(uint32_t* r, uint32_t addr) {
    asm volatile("ldmatrix.sync.aligned.m8n8.x4.shared.b16 {%0,%1,%2,%3}, [%4];"
                 : "=r"(r[0]), "=r"(r[1]), "=r"(r[2]), "=r"(r[3]) : "r"(addr));
}
__device__ __forceinline__ void mma_f16(float* c, const uint32_t* a, const uint32_t* b) {
    asm volatile(
        "mma.sync.aligned.m16n8k16.row.col.f32.f16.f16.f32 "
        "{%0,%1,%2,%3}, {%4,%5,%6,%7}, {%8,%9}, {%0,%1,%2,%3};"
        : "+f"(c[0]), "+f"(c[1]), "+f"(c[2]), "+f"(c[3])
        : "r"(a[0]), "r"(a[1]), "r"(a[2]), "r"(a[3]), "r"(b[0]), "r"(b[1]));
}

// ---------------- transpose all 4 weights -> g_wT fp16 [n][k] ----------------
__global__ __launch_bounds__(256)
void transpose_all(const float* __restrict__ wq, const float* __restrict__ wk,
                   const float* __restrict__ wv, const float* __restrict__ wo,
                   __half* __restrict__ wT)
{
    __shared__ float t[32][33];
    const float* W = (blockIdx.z == 0) ? wq : (blockIdx.z == 1) ? wk
                    : (blockIdx.z == 2) ? wv : wo;
    __half* out = wT + (size_t)blockIdx.z * DIM * DIM;
    const int c0 = blockIdx.x * 32, r0 = blockIdx.y * 32;
    const int tx = threadIdx.x, ty = threadIdx.y;
#pragma unroll
    for (int j = 0; j < 4; j++)
        t[ty + 8*j][tx] = W[(size_t)(r0 + ty + 8*j) * DIM + c0 + tx];
    __syncthreads();
#pragma unroll
    for (int j = 0; j < 4; j++)
        out[(size_t)(c0 + ty + 8*j) * DIM + (r0 + tx)] = __float2half_rn(t[tx][ty + 8*j]);
}

// ---------------- fp32 -> fp16 convert ----------------
__global__ __launch_bounds__(256)
void cvt16(const float* __restrict__ x, __half* __restrict__ hi, int n4)
{
    int i = blockIdx.x * 256 + threadIdx.x;
    if (i >= n4) return;
    float4 v = ((const float4*)x)[i];
    __half2 H0; H0.x = __float2half_rn(v.x); H0.y = __float2half_rn(v.y);
    __half2 H1; H1.x = __float2half_rn(v.z); H1.y = __float2half_rn(v.w);
    ((__half2*)hi)[2*i]   = H0;
    ((__half2*)hi)[2*i+1] = H1;
}

// ---------------- fp16 warp-MMA GEMM: C = A @ B^T ----------------
// CTA 128x128, BK=32, 6-stage cp.async, pairwise groups, one barrier per 2 iters,
// 8 warps of 32x64, 2 CTAs/SM.
#define TILEB  8192              // 128 rows x 64 bytes
#define STAGEB (2*TILEB)         // A, B
#define GSMEM  (6*STAGEB)        // 98304

__device__ __forceinline__ uint32_t swz_addr(uint32_t tile, int row, int chunk) {
    return tile + row * 64 + (((uint32_t)(chunk ^ ((row >> 1) & 3))) << 4);
}
__device__ __forceinline__ void ld_tile(uint32_t sdst, const __half* g,
                                        int grow0, int k0, int lrow, int lc0)
{
    const __half* src = g + (size_t)(grow0 + lrow) * DIM + k0 + lc0 * 8;
    cp16(swz_addr(sdst, lrow, lc0),     src);
    cp16(swz_addr(sdst, lrow, lc0 + 1), src + 8);
}

__global__ __launch_bounds__(256, 2)
void gemm_f16(const __half* __restrict__ a, const __half* __restrict__ b,
              float* __restrict__ C, int ldc)
{
    extern __shared__ char smem[];
    const uint32_t sbase = smem_u32(smem);
    const int tid  = threadIdx.x;
    const int lane = tid & 31;
    const int wid  = tid >> 5;
    const int wm   = wid >> 1;          // 0..3 -> 32-row strip
    const int wn   = wid & 1;           // 0..1 -> 64-col strip
    const int m0 = blockIdx.y * 128;
    const int n0 = blockIdx.x * 128;

    const int lrow = tid >> 1;          // 0..127
    const int lc0  = (tid & 1) * 2;     // 0 or 2

    // fragment addressing
    int arow[2], browx[4];
#pragma unroll
    for (int mt = 0; mt < 2; mt++) arow[mt] = wm * 32 + mt * 16 + (lane & 15);
#pragma unroll
    for (int p = 0; p < 4; p++)
        browx[p] = wn * 64 + p * 16 + ((lane >> 4) << 3) + (lane & 7);
    const int ac = lane >> 4;           // A chunk selector
    const int bc = (lane >> 3) & 1;     // B chunk selector

    float acc[2][8][4];
#pragma unroll
    for (int mt = 0; mt < 2; mt++)
#pragma unroll
        for (int nt = 0; nt < 8; nt++)
#pragma unroll
            for (int q = 0; q < 4; q++) acc[mt][nt][q] = 0.0f;

    // prologue: 2 groups, each covering 2 stages (pairs 0 and 1)
#pragma unroll
    for (int g = 0; g < 2; g++) {
#pragma unroll
        for (int s = 0; s < 2; s++) {
            const int st_i = g * 2 + s;
            const uint32_t st = sbase + st_i * STAGEB;
            const int k0 = st_i * 32;
            ld_tile(st,         a, m0, k0, lrow, lc0);
            ld_tile(st + TILEB, b, n0, k0, lrow, lc0);
        }
        cp_commit();
    }

    const int NPAIR = DIM / 64;         // 16 pairs (32 K-iterations)
    for (int p = 0; p < NPAIR; p++) {
        cp_wait1();                     // completes pair p's group
        __syncthreads();                // visibility + WAR for stages being refilled

        // prefetch pair p+2 (one group of 2 stages); empty commit keeps invariant
        if (p + 2 < NPAIR) {
            const int s0 = (2 * p + 4) % 6;           // even: 0, 2 or 4
            const int k0 = (2 * p + 4) * 32;
#pragma unroll
            for (int s = 0; s < 2; s++) {
                const uint32_t st = sbase + (s0 + s) * STAGEB;
                ld_tile(st,         a, m0, k0 + s * 32, lrow, lc0);
                ld_tile(st + TILEB, b, n0, k0 + s * 32, lrow, lc0);
            }
        }
        cp_commit();

        // compute both stages of pair p
#pragma unroll
        for (int s = 0; s < 2; s++) {
            const uint32_t st = sbase + ((2 * p + s) % 6) * STAGEB;
            const uint32_t sA = st;
            const uint32_t sB = st + TILEB;
#pragma unroll
            for (int kh = 0; kh < 2; kh++) {
                uint32_t fB[4][4], fA[2][4];
#pragma unroll
                for (int q = 0; q < 4; q++)
                    ldm_x4(fB[q], swz_addr(sB, browx[q], kh * 2 + bc));
#pragma unroll
                for (int mt = 0; mt < 2; mt++)
                    ldm_x4(fA[mt], swz_addr(sA, arow[mt], kh * 2 + ac));
#pragma unroll
                for (int mt = 0; mt < 2; mt++)
#pragma unroll
                    for (int q = 0; q < 4; q++) {
                        mma_f16(acc[mt][q*2],     fA[mt], &fB[q][0]);
                        mma_f16(acc[mt][q*2 + 1], fA[mt], &fB[q][2]);
                    }
            }
        }
    }

    const int erow = lane >> 2;
    const int ecol = (lane & 3) * 2;
#pragma unroll
    for (int mt = 0; mt < 2; mt++) {
#pragma unroll
        for (int nt = 0; nt < 8; nt++) {
            const int r0 = m0 + wm * 32 + mt * 16 + erow;
            const int c0 = n0 + wn * 64 + nt * 8 + ecol;
            float2 v0 = {acc[mt][nt][0], acc[mt][nt][1]};
            float2 v1 = {acc[mt][nt][2], acc[mt][nt][3]};
            *(float2*)(C + (size_t)r0 * ldc + c0)       = v0;
            *(float2*)(C + (size_t)(r0 + 8) * ldc + c0) = v1;
        }
    }
}

// ---------------- per-row rsqrt factors for q/k slices (read-only pass) ----------------
__global__ __launch_bounds__(256)
void normfact_kernel(const float* __restrict__ qkv, float* __restrict__ rsq,
                     float* __restrict__ rsk)
{
    const int row = blockIdx.x;
    const int tid = threadIdx.x;
    const float* xr = qkv + (size_t)row * NQKV + blockIdx.y * DIM;

    float4 v = *(const float4*)(xr + tid * 4);
    float ss = v.x*v.x + v.y*v.y + v.z*v.z + v.w*v.w;

    __shared__ float red[8];
#pragma unroll
    for (int o = 16; o; o >>= 1) ss += __shfl_xor_sync(0xFFFFFFFFu, ss, o);
    if ((tid & 31) == 0) red[tid >> 5] = ss;
    __syncthreads();
    if (tid < 32) {
        float s = (tid < 8) ? red[tid] : 0.0f;
#pragma unroll
        for (int o = 4; o; o >>= 1) s += __shfl_xor_sync(0xFFFFFFFFu, s, o);
        if (tid == 0) {
            float rs = rsqrtf(s * (1.0f / DIM) + EPSV);
            (blockIdx.y == 0 ? rsq : rsk)[row] = rs;
        }
    }
}

// ---------------- banded attention with fused norm; fp16 out ----------------
#define ASMEM (2 * 80 * 132 * 4)

__global__ __launch_bounds__(256)
void attn_kernel(const float* __restrict__ qkv, const float* __restrict__ rsq,
                 const float* __restrict__ rsk, const float* __restrict__ qnw,
                 const float* __restrict__ knw, __half* __restrict__ yh)
{
    extern __shared__ float sm[];
    float* ks = sm;
    float* vs = sm + 80 * 132;
    const int tid  = threadIdx.x;
    const int lane = tid & 31;
    const int wid  = tid >> 5;
    const int qb = blockIdx.x * 64;
    const int h  = blockIdx.y;
    const int b  = blockIdx.z;

    const float* kbase = qkv + (size_t)(b * SEQ) * NQKV + DIM     + h * HD;
    const float* vbase = qkv + (size_t)(b * SEQ) * NQKV + 2 * DIM + h * HD;
    const float4* kw4p = (const float4*)(knw + h * HD);

    for (int idx = tid; idx < 80 * 32; idx += 256) {
        const int r = idx >> 5, c = idx & 31;
        const int gr = qb - WIN + r;
        if (gr >= 0) {
            const float f = rsk[b * SEQ + gr];
            float4 kv = ((const float4*)(kbase + (size_t)gr * NQKV))[c];
            float4 w4 = kw4p[c];
            kv.x *= f * w4.x; kv.y *= f * w4.y; kv.z *= f * w4.z; kv.w *= f * w4.w;
            ((float4*)(ks + r * 132))[c] = kv;
            ((float4*)(vs + r * 132))[c] = ((const float4*)(vbase + (size_t)gr * NQKV))[c];
        }
    }
    __syncthreads();

    const float scale = 0.08838834764831845f;   // 1/sqrt(128)
    const float slope = exp2f(-(float)h);       // ALiBi slope, H=8
    const float4 qw4 = ((const float4*)(qnw + h * HD))[lane];

#pragma unroll 1
    for (int it = 0; it < 8; it++) {
        const int t = qb + it * 8 + wid;
        float4 q = *(const float4*)(qkv + (size_t)(b * SEQ + t) * NQKV + h * HD + lane * 4);
        const float qf = rsq[b * SEQ + t] * scale;
        q.x *= qf * qw4.x; q.y *= qf * qw4.y; q.z *= qf * qw4.z; q.w *= qf * qw4.w;

        float sc[WIN + 1];
        float mx = -1e30f;
#pragma unroll
        for (int jj = 0; jj <= WIN; jj++) {
            const int j = t - WIN + jj;
            float s = -1e30f;
            if (j >= 0) {
                const int sr = j - qb + WIN;
                const float4 k4 = *(const float4*)(ks + sr * 132 + lane * 4);
                float d = q.x*k4.x + q.y*k4.y + q.z*k4.z + q.w*k4.w;
#pragma unroll
                for (int o = 16; o; o >>= 1) d += __shfl_xor_sync(0xFFFFFFFFu, d, o);
                s = d + slope * (float)(j - t);
            }
            sc[jj] = s;
            mx = fmaxf(mx, s);
        }
        float l = 0.0f;
#pragma unroll
        for (int jj = 0; jj <= WIN; jj++) {
            float e = __expf(sc[jj] - mx);
            sc[jj] = e;
            l += e;
        }
        const float inv = 1.0f / l;

        float4 acc = {0.f, 0.f, 0.f, 0.f};
#pragma unroll
        for (int jj = 0; jj <= WIN; jj++) {
            const int j = t - WIN + jj;
            if (j >= 0) {
                const int sr = j - qb + WIN;
                const float4 v4 = *(const float4*)(vs + sr * 132 + lane * 4);
                const float p = sc[jj] * inv;
                acc.x = fmaf(p, v4.x, acc.x);
                acc.y = fmaf(p, v4.y, acc.y);
                acc.z = fmaf(p, v4.z, acc.z);
                acc.w = fmaf(p, v4.w, acc.w);
            }
        }

        const size_t off = (size_t)(b * SEQ + t) * DIM + h * HD + lane * 4;
        __half2 H0; H0.x = __float2half_rn(acc.x); H0.y = __float2half_rn(acc.y);
        __half2 H1; H1.x = __float2half_rn(acc.z); H1.y = __float2half_rn(acc.w);
        ((__half2*)(yh + off))[0] = H0;
        ((__half2*)(yh + off))[1] = H1;
    }
}

// ---------------- launch ----------------
extern "C" void kernel_launch(void* const* d_in, const int* in_sizes, int n_in,
                              void* d_out, int out_size)
{
    const float* x   = (const float*)d_in[0];
    const float* wq  = (const float*)d_in[1];
    const float* wk  = (const float*)d_in[2];
    const float* wv  = (const float*)d_in[3];
    const float* wo  = (const float*)d_in[4];
    const float* qnw = (const float*)d_in[5];
    const float* knw = (const float*)d_in[6];
    float* out       = (float*)d_out;

    __half *wT, *xh, *yh;
    float *qkv, *rsq, *rsk;
    cudaGetSymbolAddress((void**)&wT,  g_wT);
    cudaGetSymbolAddress((void**)&xh,  g_xh);
    cudaGetSymbolAddress((void**)&qkv, g_qkv);
    cudaGetSymbolAddress((void**)&yh,  g_yh);
    cudaGetSymbolAddress((void**)&rsq, g_rsq);
    cudaGetSymbolAddress((void**)&rsk, g_rsk);

    cudaFuncSetAttribute(gemm_f16,    cudaFuncAttributeMaxDynamicSharedMemorySize, GSMEM);
    cudaFuncSetAttribute(attn_kernel, cudaFuncAttributeMaxDynamicSharedMemorySize, ASMEM);

    // 1) transpose all weights -> fp16 [n][k], rows: [wq|wk|wv|wo]
    dim3 tgrid(DIM/32, DIM/32, 4), tblk(32, 8);
    transpose_all<<<tgrid, tblk>>>(wq, wk, wv, wo, wT);

    // 2) convert x to fp16
    cvt16<<<(MR*DIM/4 + 255)/256, 256>>>(x, xh, MR*DIM/4);

    // 3) fused QKV projection: [8192x1024] @ [1024x3072]
    dim3 qkvgrid(NQKV/128, MR/128);
    gemm_f16<<<qkvgrid, 256, GSMEM>>>(xh, wT, qkv, NQKV);

    // 4) per-row norm factors (read-only)
    dim3 ngrid(MR, 2);
    normfact_kernel<<<ngrid, 256>>>(qkv, rsq, rsk);

    // 5) banded attention with fused norm -> y fp16
    dim3 agrid(SEQ/64, NH, BATCH);
    attn_kernel<<<agrid, 256, ASMEM>>>(qkv, rsq, rsk, qnw, knw, yh);

    // 6) output projection: [8192x1024] @ [1024x1024]
    dim3 ogrid(DIM/128, MR/128);
    gemm_f16<<<ogrid, 256, GSMEM>>>(yh, wT + (size_t)3072*DIM, out, DIM);
}

// round 12
// speedup vs baseline: 1.0996x; 1.0756x over previous
#include <cuda_runtime.h>
#include <cuda_fp16.h>
#include <math.h>
#include <stdint.h>

// ---------------- problem constants ----------------
#define BATCH 4
#define SEQ   2048
#define DIM   1024
#define NH    8
#define HD    128
#define WIN   16
#define EPSV  1e-6f
#define MR    (BATCH*SEQ)   // 8192
#define NQKV  3072
#define NW    4096          // transposed weight rows: 3072 qkv + 1024 wo

// ---------------- device scratch ----------------
__device__ __align__(16) __half g_wT[NW*DIM];     // fp16 transposed weights [n][k]
__device__ __align__(16) __half g_xh[MR*DIM];
__device__ __align__(16) __half g_qkvh[MR*NQKV];  // fp16 qkv
__device__ __align__(16) __half g_yh[MR*DIM];
__device__ __align__(16) float  g_rsq[MR];
__device__ __align__(16) float  g_rsk[MR];

// ---------------- PTX helpers ----------------
__device__ __forceinline__ uint32_t smem_u32(const void* p) {
    uint32_t a;
    asm("{ .reg .u64 t; cvta.to.shared.u64 t, %1; cvt.u32.u64 %0, t; }" : "=r"(a) : "l"(p));
    return a;
}
__device__ __forceinline__ void cp16(uint32_t d, const void* s) {
    asm volatile("cp.async.cg.shared.global [%0], [%1], 16;" :: "r"(d), "l"(s));
}
__device__ __forceinline__ void cp_commit() { asm volatile("cp.async.commit_group;" ::: "memory"); }
__device__ __forceinline__ void cp_wait2()  { asm volatile("cp.async.wait_group 2;" ::: "memory"); }
__device__ __forceinline__ void cp_wait1()  { asm volatile("cp.async.wait_group 1;" ::: "memory"); }
__device__ __forceinline__ void cp_wait0()  { asm volatile("cp.async.wait_group 0;" ::: "memory"); }

__device__ __forceinline__ void ldm_x4(uint32_t* r, uint32_t addr) {
    asm volatile("ldmatrix.sync.aligned.m8n8.x4.shared.b16 {%0,%1,%2,%3}, [%4];"
                 : "=r"(r[0]), "=r"(r[1]), "=r"(r[2]), "=r"(r[3]) : "r"(addr));
}
__device__ __forceinline__ void mma_f16(float* c, const uint32_t* a, const uint32_t* b) {
    asm volatile(
        "mma.sync.aligned.m16n8k16.row.col.f32.f16.f16.f32 "
        "{%0,%1,%2,%3}, {%4,%5,%6,%7}, {%8,%9}, {%0,%1,%2,%3};"
        : "+f"(c[0]), "+f"(c[1]), "+f"(c[2]), "+f"(c[3])
        : "r"(a[0]), "r"(a[1]), "r"(a[2]), "r"(a[3]), "r"(b[0]), "r"(b[1]));
}
__device__ __forceinline__ float4 h4_to_f4(uint2 u) {
    __half2 a = *(__half2*)&u.x, b = *(__half2*)&u.y;
    float2 f0 = __half22float2(a), f1 = __half22float2(b);
    float4 r; r.x = f0.x; r.y = f0.y; r.z = f1.x; r.w = f1.y;
    return r;
}

// ---------------- transpose all 4 weights -> g_wT fp16 [n][k] ----------------
__global__ __launch_bounds__(256)
void transpose_all(const float* __restrict__ wq, const float* __restrict__ wk,
                   const float* __restrict__ wv, const float* __restrict__ wo,
                   __half* __restrict__ wT)
{
    __shared__ float t[32][33];
    const float* W = (blockIdx.z == 0) ? wq : (blockIdx.z == 1) ? wk
                    : (blockIdx.z == 2) ? wv : wo;
    __half* out = wT + (size_t)blockIdx.z * DIM * DIM;
    const int c0 = blockIdx.x * 32, r0 = blockIdx.y * 32;
    const int tx = threadIdx.x, ty = threadIdx.y;
#pragma unroll
    for (int j = 0; j < 4; j++)
        t[ty + 8*j][tx] = W[(size_t)(r0 + ty + 8*j) * DIM + c0 + tx];
    __syncthreads();
#pragma unroll
    for (int j = 0; j < 4; j++)
        out[(size_t)(c0 + ty + 8*j) * DIM + (r0 + tx)] = __float2half_rn(t[tx][ty + 8*j]);
}

// ---------------- fp32 -> fp16 convert ----------------
__global__ __launch_bounds__(256)
void cvt16(const float* __restrict__ x, __half* __restrict__ hi, int n4)
{
    int i = blockIdx.x * 256 + threadIdx.x;
    if (i >= n4) return;
    float4 v = ((const float4*)x)[i];
    __half2 H0; H0.x = __float2half_rn(v.x); H0.y = __float2half_rn(v.y);
    __half2 H1; H1.x = __float2half_rn(v.z); H1.y = __float2half_rn(v.w);
    ((__half2*)hi)[2*i]   = H0;
    ((__half2*)hi)[2*i+1] = H1;
}

// ---------------- fp16 warp-MMA GEMM: C = A @ B^T (R9 config) ----------------
// CTA 128x128, BK=32, 4-stage cp.async, 8 warps of 32x64, 2 CTAs/SM.
// OUT16=1 -> fp16 C, OUT16=0 -> fp32 C.
#define TILEB  8192              // 128 rows x 64 bytes
#define STAGEB (2*TILEB)         // A, B
#define GSMEM  (4*STAGEB)        // 65536

__device__ __forceinline__ uint32_t swz_addr(uint32_t tile, int row, int chunk) {
    return tile + row * 64 + (((uint32_t)(chunk ^ ((row >> 1) & 3))) << 4);
}
__device__ __forceinline__ void ld_tile(uint32_t sdst, const __half* g,
                                        int grow0, int k0, int lrow, int lc0)
{
    const __half* src = g + (size_t)(grow0 + lrow) * DIM + k0 + lc0 * 8;
    cp16(swz_addr(sdst, lrow, lc0),     src);
    cp16(swz_addr(sdst, lrow, lc0 + 1), src + 8);
}

template<int OUT16>
__global__ __launch_bounds__(256, 2)
void gemm_f16(const __half* __restrict__ a, const __half* __restrict__ b,
              void* __restrict__ Cv, int ldc)
{
    extern __shared__ char smem[];
    const uint32_t sbase = smem_u32(smem);
    const int tid  = threadIdx.x;
    const int lane = tid & 31;
    const int wid  = tid >> 5;
    const int wm   = wid >> 1;          // 0..3 -> 32-row strip
    const int wn   = wid & 1;           // 0..1 -> 64-col strip
    const int m0 = blockIdx.y * 128;
    const int n0 = blockIdx.x * 128;

    const int lrow = tid >> 1;          // 0..127
    const int lc0  = (tid & 1) * 2;     // 0 or 2

    int arow[2], browx[4];
#pragma unroll
    for (int mt = 0; mt < 2; mt++) arow[mt] = wm * 32 + mt * 16 + (lane & 15);
#pragma unroll
    for (int p = 0; p < 4; p++)
        browx[p] = wn * 64 + p * 16 + ((lane >> 4) << 3) + (lane & 7);
    const int ac = lane >> 4;
    const int bc = (lane >> 3) & 1;

    float acc[2][8][4];
#pragma unroll
    for (int mt = 0; mt < 2; mt++)
#pragma unroll
        for (int nt = 0; nt < 8; nt++)
#pragma unroll
            for (int q = 0; q < 4; q++) acc[mt][nt][q] = 0.0f;

#pragma unroll
    for (int s = 0; s < 3; s++) {
        const uint32_t st = sbase + s * STAGEB;
        const int k0 = s * 32;
        ld_tile(st,         a, m0, k0, lrow, lc0);
        ld_tile(st + TILEB, b, n0, k0, lrow, lc0);
        cp_commit();
    }

    const int NIT = DIM / 32;           // 32
    for (int i = 0; i < NIT; i++) {
        if (i < NIT - 2)      cp_wait2();
        else if (i == NIT-2)  cp_wait1();
        else                  cp_wait0();
        __syncthreads();

        if (i + 3 < NIT) {
            const uint32_t st = sbase + ((i + 3) & 3) * STAGEB;
            const int k0 = (i + 3) * 32;
            ld_tile(st,         a, m0, k0, lrow, lc0);
            ld_tile(st + TILEB, b, n0, k0, lrow, lc0);
            cp_commit();
        }

        const uint32_t st = sbase + (i & 3) * STAGEB;
        const uint32_t sA = st;
        const uint32_t sB = st + TILEB;

#pragma unroll
        for (int kh = 0; kh < 2; kh++) {
            uint32_t fB[4][4], fA[2][4];
#pragma unroll
            for (int p = 0; p < 4; p++)
                ldm_x4(fB[p], swz_addr(sB, browx[p], kh * 2 + bc));
#pragma unroll
            for (int mt = 0; mt < 2; mt++)
                ldm_x4(fA[mt], swz_addr(sA, arow[mt], kh * 2 + ac));
#pragma unroll
            for (int mt = 0; mt < 2; mt++)
#pragma unroll
                for (int p = 0; p < 4; p++) {
                    mma_f16(acc[mt][p*2],     fA[mt], &fB[p][0]);
                    mma_f16(acc[mt][p*2 + 1], fA[mt], &fB[p][2]);
                }
        }
    }

    const int erow = lane >> 2;
    const int ecol = (lane & 3) * 2;
#pragma unroll
    for (int mt = 0; mt < 2; mt++) {
#pragma unroll
        for (int nt = 0; nt < 8; nt++) {
            const int r0 = m0 + wm * 32 + mt * 16 + erow;
            const int c0 = n0 + wn * 64 + nt * 8 + ecol;
            if (OUT16) {
                __half* C = (__half*)Cv;
                __half2 h0; h0.x = __float2half_rn(acc[mt][nt][0]); h0.y = __float2half_rn(acc[mt][nt][1]);
                __half2 h1; h1.x = __float2half_rn(acc[mt][nt][2]); h1.y = __float2half_rn(acc[mt][nt][3]);
                *(__half2*)(C + (size_t)r0 * ldc + c0)       = h0;
                *(__half2*)(C + (size_t)(r0 + 8) * ldc + c0) = h1;
            } else {
                float* C = (float*)Cv;
                float2 v0 = {acc[mt][nt][0], acc[mt][nt][1]};
                float2 v1 = {acc[mt][nt][2], acc[mt][nt][3]};
                *(float2*)(C + (size_t)r0 * ldc + c0)       = v0;
                *(float2*)(C + (size_t)(r0 + 8) * ldc + c0) = v1;
            }
        }
    }
}

// ---------------- per-row rsqrt factors; warp per row, fp16 input ----------------
__global__ __launch_bounds__(256)
void normfact_kernel(const __half* __restrict__ qkvh, float* __restrict__ rsq,
                     float* __restrict__ rsk)
{
    const int wid  = threadIdx.x >> 5;
    const int lane = threadIdx.x & 31;
    const int row  = blockIdx.x * 8 + wid;
    const __half* xr = qkvh + (size_t)row * NQKV + blockIdx.y * DIM;

    float ss = 0.0f;
#pragma unroll
    for (int j = 0; j < 4; j++) {
        uint4 u = ((const uint4*)xr)[lane + j * 32];   // 8 halves
        const __half2* hp = (const __half2*)&u;
#pragma unroll
        for (int q = 0; q < 4; q++) {
            float2 f = __half22float2(hp[q]);
            ss += f.x * f.x + f.y * f.y;
        }
    }
#pragma unroll
    for (int o = 16; o; o >>= 1) ss += __shfl_xor_sync(0xFFFFFFFFu, ss, o);
    if (lane == 0) {
        float rs = rsqrtf(ss * (1.0f / DIM) + EPSV);
        (blockIdx.y == 0 ? rsq : rsk)[row] = rs;
    }
}

// ---------------- banded attention, fp16 qkv in, fused norm; fp16 out ----------------
#define ASMEM (2 * 80 * 132 * 4)

__global__ __launch_bounds__(256)
void attn_kernel(const __half* __restrict__ qkvh, const float* __restrict__ rsq,
                 const float* __restrict__ rsk, const float* __restrict__ qnw,
                 const float* __restrict__ knw, __half* __restrict__ yh)
{
    extern __shared__ float sm[];
    float* ks = sm;
    float* vs = sm + 80 * 132;
    const int tid  = threadIdx.x;
    const int lane = tid & 31;
    const int wid  = tid >> 5;
    const int qb = blockIdx.x * 64;
    const int h  = blockIdx.y;
    const int b  = blockIdx.z;

    const __half* kbase = qkvh + (size_t)(b * SEQ) * NQKV + DIM     + h * HD;
    const __half* vbase = qkvh + (size_t)(b * SEQ) * NQKV + 2 * DIM + h * HD;
    const float4* kw4p = (const float4*)(knw + h * HD);

    for (int idx = tid; idx < 80 * 32; idx += 256) {
        const int r = idx >> 5, c = idx & 31;
        const int gr = qb - WIN + r;
        if (gr >= 0) {
            const float f = rsk[b * SEQ + gr];
            float4 kv = h4_to_f4(((const uint2*)(kbase + (size_t)gr * NQKV))[c]);
            float4 w4 = kw4p[c];
            kv.x *= f * w4.x; kv.y *= f * w4.y; kv.z *= f * w4.z; kv.w *= f * w4.w;
            ((float4*)(ks + r * 132))[c] = kv;
            ((float4*)(vs + r * 132))[c] = h4_to_f4(((const uint2*)(vbase + (size_t)gr * NQKV))[c]);
        }
    }
    __syncthreads();

    const float scale = 0.08838834764831845f;   // 1/sqrt(128)
    const float slope = exp2f(-(float)h);       // ALiBi slope, H=8
    const float4 qw4 = ((const float4*)(qnw + h * HD))[lane];

#pragma unroll 1
    for (int it = 0; it < 8; it++) {
        const int t = qb + it * 8 + wid;
        float4 q = h4_to_f4(((const uint2*)(qkvh + (size_t)(b * SEQ + t) * NQKV + h * HD))[lane]);
        const float qf = rsq[b * SEQ + t] * scale;
        q.x *= qf * qw4.x; q.y *= qf * qw4.y; q.z *= qf * qw4.z; q.w *= qf * qw4.w;

        float sc[WIN + 1];
        float mx = -1e30f;
#pragma unroll
        for (int jj = 0; jj <= WIN; jj++) {
            const int j = t - WIN + jj;
            float s = -1e30f;
            if (j >= 0) {
                const int sr = j - qb + WIN;
                const float4 k4 = *(const float4*)(ks + sr * 132 + lane * 4);
                float d = q.x*k4.x + q.y*k4.y + q.z*k4.z + q.w*k4.w;
#pragma unroll
                for (int o = 16; o; o >>= 1) d += __shfl_xor_sync(0xFFFFFFFFu, d, o);
                s = d + slope * (float)(j - t);
            }
            sc[jj] = s;
            mx = fmaxf(mx, s);
        }
        float l = 0.0f;
#pragma unroll
        for (int jj = 0; jj <= WIN; jj++) {
            float e = __expf(sc[jj] - mx);
            sc[jj] = e;
            l += e;
        }
        const float inv = 1.0f / l;

        float4 acc = {0.f, 0.f, 0.f, 0.f};
#pragma unroll
        for (int jj = 0; jj <= WIN; jj++) {
            const int j = t - WIN + jj;
            if (j >= 0) {
                const int sr = j - qb + WIN;
                const float4 v4 = *(const float4*)(vs + sr * 132 + lane * 4);
                const float p = sc[jj] * inv;
                acc.x = fmaf(p, v4.x, acc.x);
                acc.y = fmaf(p, v4.y, acc.y);
                acc.z = fmaf(p, v4.z, acc.z);
                acc.w = fmaf(p, v4.w, acc.w);
            }
        }

        const size_t off = (size_t)(b * SEQ + t) * DIM + h * HD + lane * 4;
        __half2 H0; H0.x = __float2half_rn(acc.x); H0.y = __float2half_rn(acc.y);
        __half2 H1; H1.x = __float2half_rn(acc.z); H1.y = __float2half_rn(acc.w);
        ((__half2*)(yh + off))[0] = H0;
        ((__half2*)(yh + off))[1] = H1;
    }
}

// ---------------- launch ----------------
extern "C" void kernel_launch(void* const* d_in, const int* in_sizes, int n_in,
                              void* d_out, int out_size)
{
    const float* x   = (const float*)d_in[0];
    const float* wq  = (const float*)d_in[1];
    const float* wk  = (const float*)d_in[2];
    const float* wv  = (const float*)d_in[3];
    const float* wo  = (const float*)d_in[4];
    const float* qnw = (const float*)d_in[5];
    const float* knw = (const float*)d_in[6];
    float* out       = (float*)d_out;

    __half *wT, *xh, *qkvh, *yh;
    float *rsq, *rsk;
    cudaGetSymbolAddress((void**)&wT,   g_wT);
    cudaGetSymbolAddress((void**)&xh,   g_xh);
    cudaGetSymbolAddress((void**)&qkvh, g_qkvh);
    cudaGetSymbolAddress((void**)&yh,   g_yh);
    cudaGetSymbolAddress((void**)&rsq,  g_rsq);
    cudaGetSymbolAddress((void**)&rsk,  g_rsk);

    cudaFuncSetAttribute(gemm_f16<0>, cudaFuncAttributeMaxDynamicSharedMemorySize, GSMEM);
    cudaFuncSetAttribute(gemm_f16<1>, cudaFuncAttributeMaxDynamicSharedMemorySize, GSMEM);
    cudaFuncSetAttribute(attn_kernel, cudaFuncAttributeMaxDynamicSharedMemorySize, ASMEM);

    // 1) transpose all weights -> fp16 [n][k], rows: [wq|wk|wv|wo]
    dim3 tgrid(DIM/32, DIM/32, 4), tblk(32, 8);
    transpose_all<<<tgrid, tblk>>>(wq, wk, wv, wo, wT);

    // 2) convert x to fp16
    cvt16<<<(MR*DIM/4 + 255)/256, 256>>>(x, xh, MR*DIM/4);

    // 3) fused QKV projection -> fp16: [8192x1024] @ [1024x3072]
    dim3 qkvgrid(NQKV/128, MR/128);
    gemm_f16<1><<<qkvgrid, 256, GSMEM>>>(xh, wT, qkvh, NQKV);

    // 4) per-row norm factors (warp per row)
    dim3 ngrid(MR/8, 2);
    normfact_kernel<<<ngrid, 256>>>(qkvh, rsq, rsk);

    // 5) banded attention with fused norm -> y fp16
    dim3 agrid(SEQ/64, NH, BATCH);
    attn_kernel<<<agrid, 256, ASMEM>>>(qkvh, rsq, rsk, qnw, knw, yh);

    // 6) output projection -> fp32 out: [8192x1024] @ [1024x1024]
    dim3 ogrid(DIM/128, MR/128);
    gemm_f16<0><<<ogrid, 256, GSMEM>>>(yh, wT + (size_t)3072*DIM, out, DIM);
}

// round 13
// speedup vs baseline: 1.1073x; 1.0070x over previous
#include <cuda_runtime.h>
#include <cuda_fp16.h>
#include <math.h>
#include <stdint.h>

// ---------------- problem constants ----------------
#define BATCH 4
#define SEQ   2048
#define DIM   1024
#define NH    8
#define HD    128
#define WIN   16
#define EPSV  1e-6f
#define MR    (BATCH*SEQ)   // 8192
#define NQKV  3072
#define NW    4096

// ---------------- device scratch ----------------
__device__ __align__(16) __half g_wT[NW*DIM];     // fp16 transposed weights [n][k]
__device__ __align__(16) __half g_xh[MR*DIM];
__device__ __align__(16) __half g_qkvh[MR*NQKV];  // fp16 qkv
__device__ __align__(16) __half g_yh[MR*DIM];
__device__ __align__(16) float  g_ssp[MR*16];     // per-(row, n-block) partial sum-of-squares
__device__ __align__(16) float  g_rsq[MR];
__device__ __align__(16) float  g_rsk[MR];

// ---------------- PTX helpers ----------------
__device__ __forceinline__ uint32_t smem_u32(const void* p) {
    uint32_t a;
    asm("{ .reg .u64 t; cvta.to.shared.u64 t, %1; cvt.u32.u64 %0, t; }" : "=r"(a) : "l"(p));
    return a;
}
__device__ __forceinline__ void cp16(uint32_t d, const void* s) {
    asm volatile("cp.async.cg.shared.global [%0], [%1], 16;" :: "r"(d), "l"(s));
}
__device__ __forceinline__ void cp_commit() { asm volatile("cp.async.commit_group;" ::: "memory"); }
__device__ __forceinline__ void cp_wait2()  { asm volatile("cp.async.wait_group 2;" ::: "memory"); }
__device__ __forceinline__ void cp_wait1()  { asm volatile("cp.async.wait_group 1;" ::: "memory"); }
__device__ __forceinline__ void cp_wait0()  { asm volatile("cp.async.wait_group 0;" ::: "memory"); }

__device__ __forceinline__ void ldm_x4(uint32_t* r, uint32_t addr) {
    asm volatile("ldmatrix.sync.aligned.m8n8.x4.shared.b16 {%0,%1,%2,%3}, [%4];"
                 : "=r"(r[0]), "=r"(r[1]), "=r"(r[2]), "=r"(r[3]) : "r"(addr));
}
__device__ __forceinline__ void mma_f16(float* c, const uint32_t* a, const uint32_t* b) {
    asm volatile(
        "mma.sync.aligned.m16n8k16.row.col.f32.f16.f16.f32 "
        "{%0,%1,%2,%3}, {%4,%5,%6,%7}, {%8,%9}, {%0,%1,%2,%3};"
        : "+f"(c[0]), "+f"(c[1]), "+f"(c[2]), "+f"(c[3])
        : "r"(a[0]), "r"(a[1]), "r"(a[2]), "r"(a[3]), "r"(b[0]), "r"(b[1]));
}
__device__ __forceinline__ float4 h4_to_f4(uint2 u) {
    __half2 a = *(__half2*)&u.x, b = *(__half2*)&u.y;
    float2 f0 = __half22float2(a), f1 = __half22float2(b);
    float4 r; r.x = f0.x; r.y = f0.y; r.z = f1.x; r.w = f1.y;
    return r;
}

// ---------------- prep: weights transpose->fp16 (z<4) + x convert (z>=4) ----------------
__global__ __launch_bounds__(256)
void prep_kernel(const float* __restrict__ x,
                 const float* __restrict__ wq, const float* __restrict__ wk,
                 const float* __restrict__ wv, const float* __restrict__ wo,
                 __half* __restrict__ wT, __half* __restrict__ xh)
{
    if (blockIdx.z < 4) {
        __shared__ float t[32][33];
        const float* W = (blockIdx.z == 0) ? wq : (blockIdx.z == 1) ? wk
                        : (blockIdx.z == 2) ? wv : wo;
        __half* out = wT + (size_t)blockIdx.z * DIM * DIM;
        const int c0 = blockIdx.x * 32, r0 = blockIdx.y * 32;
        const int tx = threadIdx.x, ty = threadIdx.y;
#pragma unroll
        for (int j = 0; j < 4; j++)
            t[ty + 8*j][tx] = W[(size_t)(r0 + ty + 8*j) * DIM + c0 + tx];
        __syncthreads();
#pragma unroll
        for (int j = 0; j < 4; j++)
            out[(size_t)(c0 + ty + 8*j) * DIM + (r0 + tx)] = __float2half_rn(t[tx][ty + 8*j]);
    } else {
        const int tid = threadIdx.y * 32 + threadIdx.x;
        const int blocklin = (blockIdx.z - 4) * 1024 + blockIdx.y * 32 + blockIdx.x;
        const int i = blocklin * 256 + tid;            // < MR*DIM/4 exactly
        float4 v = ((const float4*)x)[i];
        __half2 H0; H0.x = __float2half_rn(v.x); H0.y = __float2half_rn(v.y);
        __half2 H1; H1.x = __float2half_rn(v.z); H1.y = __float2half_rn(v.w);
        ((__half2*)xh)[2*i]   = H0;
        ((__half2*)xh)[2*i+1] = H1;
    }
}

// ---------------- fp16 warp-MMA GEMM: C = A @ B^T (R9 config) ----------------
// CTA 128x128, BK=32, 4-stage cp.async, 8 warps of 32x64, 2 CTAs/SM.
// OUT16=1 -> fp16 C + per-row ss partials; OUT16=0 -> fp32 C.
#define TILEB  8192
#define STAGEB (2*TILEB)
#define GSMEM  (4*STAGEB)        // 65536

__device__ __forceinline__ uint32_t swz_addr(uint32_t tile, int row, int chunk) {
    return tile + row * 64 + (((uint32_t)(chunk ^ ((row >> 1) & 3))) << 4);
}
__device__ __forceinline__ void ld_tile(uint32_t sdst, const __half* g,
                                        int grow0, int k0, int lrow, int lc0)
{
    const __half* src = g + (size_t)(grow0 + lrow) * DIM + k0 + lc0 * 8;
    cp16(swz_addr(sdst, lrow, lc0),     src);
    cp16(swz_addr(sdst, lrow, lc0 + 1), src + 8);
}

template<int OUT16>
__global__ __launch_bounds__(256, 2)
void gemm_f16(const __half* __restrict__ a, const __half* __restrict__ b,
              void* __restrict__ Cv, int ldc, float* __restrict__ ssp)
{
    extern __shared__ char smem[];
    const uint32_t sbase = smem_u32(smem);
    const int tid  = threadIdx.x;
    const int lane = tid & 31;
    const int wid  = tid >> 5;
    const int wm   = wid >> 1;          // 0..3
    const int wn   = wid & 1;           // 0..1
    const int m0 = blockIdx.y * 128;
    const int n0 = blockIdx.x * 128;

    const int lrow = tid >> 1;
    const int lc0  = (tid & 1) * 2;

    int arow[2], browx[4];
#pragma unroll
    for (int mt = 0; mt < 2; mt++) arow[mt] = wm * 32 + mt * 16 + (lane & 15);
#pragma unroll
    for (int p = 0; p < 4; p++)
        browx[p] = wn * 64 + p * 16 + ((lane >> 4) << 3) + (lane & 7);
    const int ac = lane >> 4;
    const int bc = (lane >> 3) & 1;

    float acc[2][8][4];
#pragma unroll
    for (int mt = 0; mt < 2; mt++)
#pragma unroll
        for (int nt = 0; nt < 8; nt++)
#pragma unroll
            for (int q = 0; q < 4; q++) acc[mt][nt][q] = 0.0f;

#pragma unroll
    for (int s = 0; s < 3; s++) {
        const uint32_t st = sbase + s * STAGEB;
        const int k0 = s * 32;
        ld_tile(st,         a, m0, k0, lrow, lc0);
        ld_tile(st + TILEB, b, n0, k0, lrow, lc0);
        cp_commit();
    }

    const int NIT = DIM / 32;           // 32
    for (int i = 0; i < NIT; i++) {
        if (i < NIT - 2)      cp_wait2();
        else if (i == NIT-2)  cp_wait1();
        else                  cp_wait0();
        __syncthreads();

        if (i + 3 < NIT) {
            const uint32_t st = sbase + ((i + 3) & 3) * STAGEB;
            const int k0 = (i + 3) * 32;
            ld_tile(st,         a, m0, k0, lrow, lc0);
            ld_tile(st + TILEB, b, n0, k0, lrow, lc0);
            cp_commit();
        }

        const uint32_t st = sbase + (i & 3) * STAGEB;
        const uint32_t sA = st;
        const uint32_t sB = st + TILEB;

#pragma unroll
        for (int kh = 0; kh < 2; kh++) {
            uint32_t fB[4][4], fA[2][4];
#pragma unroll
            for (int p = 0; p < 4; p++)
                ldm_x4(fB[p], swz_addr(sB, browx[p], kh * 2 + bc));
#pragma unroll
            for (int mt = 0; mt < 2; mt++)
                ldm_x4(fA[mt], swz_addr(sA, arow[mt], kh * 2 + ac));
#pragma unroll
            for (int mt = 0; mt < 2; mt++)
#pragma unroll
                for (int p = 0; p < 4; p++) {
                    mma_f16(acc[mt][p*2],     fA[mt], &fB[p][0]);
                    mma_f16(acc[mt][p*2 + 1], fA[mt], &fB[p][2]);
                }
        }
    }

    const int erow = lane >> 2;
    const int ecol = (lane & 3) * 2;
#pragma unroll
    for (int mt = 0; mt < 2; mt++) {
#pragma unroll
        for (int nt = 0; nt < 8; nt++) {
            const int r0 = m0 + wm * 32 + mt * 16 + erow;
            const int c0 = n0 + wn * 64 + nt * 8 + ecol;
            if (OUT16) {
                __half* C = (__half*)Cv;
                __half2 h0; h0.x = __float2half_rn(acc[mt][nt][0]); h0.y = __float2half_rn(acc[mt][nt][1]);
                __half2 h1; h1.x = __float2half_rn(acc[mt][nt][2]); h1.y = __float2half_rn(acc[mt][nt][3]);
                *(__half2*)(C + (size_t)r0 * ldc + c0)       = h0;
                *(__half2*)(C + (size_t)(r0 + 8) * ldc + c0) = h1;
            } else {
                float* C = (float*)Cv;
                float2 v0 = {acc[mt][nt][0], acc[mt][nt][1]};
                float2 v1 = {acc[mt][nt][2], acc[mt][nt][3]};
                *(float2*)(C + (size_t)r0 * ldc + c0)       = v0;
                *(float2*)(C + (size_t)(r0 + 8) * ldc + c0) = v1;
            }
        }
    }

    if (OUT16) {
        // per-row partial sum-of-squares for this CTA's 128 columns (q/k blocks only)
        if (blockIdx.x < 16) {
            float s0 = 0.0f, s1 = 0.0f;      // rows r(mt), for mt handled below
            float* ssbuf = (float*)smem;     // 256 floats; smem free after last sync
            __syncthreads();                 // all warps done reading stages
#pragma unroll
            for (int mt = 0; mt < 2; mt++) {
                float p0 = 0.0f, p1 = 0.0f;
#pragma unroll
                for (int nt = 0; nt < 8; nt++) {
                    p0 += acc[mt][nt][0]*acc[mt][nt][0] + acc[mt][nt][1]*acc[mt][nt][1];
                    p1 += acc[mt][nt][2]*acc[mt][nt][2] + acc[mt][nt][3]*acc[mt][nt][3];
                }
                p0 += __shfl_xor_sync(0xFFFFFFFFu, p0, 1);
                p0 += __shfl_xor_sync(0xFFFFFFFFu, p0, 2);
                p1 += __shfl_xor_sync(0xFFFFFFFFu, p1, 1);
                p1 += __shfl_xor_sync(0xFFFFFFFFu, p1, 2);
                if ((lane & 3) == 0) {
                    const int rloc = wm * 32 + mt * 16 + erow;
                    ssbuf[wn * 128 + rloc]     = p0;
                    ssbuf[wn * 128 + rloc + 8] = p1;
                }
                (void)s0; (void)s1;
            }
            __syncthreads();
            if (tid < 128) {
                float s = ssbuf[tid] + ssbuf[128 + tid];
                ssp[(size_t)(m0 + tid) * 16 + blockIdx.x] = s;
            }
        }
    }
}

// ---------------- combine ss partials -> rsqrt factors ----------------
__global__ __launch_bounds__(256)
void rsfact_kernel(const float* __restrict__ ssp, float* __restrict__ rsq,
                   float* __restrict__ rsk)
{
    const int idx = blockIdx.x * 256 + threadIdx.x;    // MR*2 total
    const int row = idx >> 1;
    const int slice = idx & 1;
    const float4* p = (const float4*)(ssp + (size_t)row * 16 + slice * 8);
    float4 a = p[0], b = p[1];
    float s = a.x + a.y + a.z + a.w + b.x + b.y + b.z + b.w;
    float rs = rsqrtf(s * (1.0f / DIM) + EPSV);
    (slice == 0 ? rsq : rsk)[row] = rs;
}

// ---------------- banded attention, fp16 qkv in, fused norm; fp16 out ----------------
#define ASMEM (2 * 80 * 132 * 4)

__global__ __launch_bounds__(256)
void attn_kernel(const __half* __restrict__ qkvh, const float* __restrict__ rsq,
                 const float* __restrict__ rsk, const float* __restrict__ qnw,
                 const float* __restrict__ knw, __half* __restrict__ yh)
{
    extern __shared__ float sm[];
    float* ks = sm;
    float* vs = sm + 80 * 132;
    const int tid  = threadIdx.x;
    const int lane = tid & 31;
    const int wid  = tid >> 5;
    const int qb = blockIdx.x * 64;
    const int h  = blockIdx.y;
    const int b  = blockIdx.z;

    const __half* kbase = qkvh + (size_t)(b * SEQ) * NQKV + DIM     + h * HD;
    const __half* vbase = qkvh + (size_t)(b * SEQ) * NQKV + 2 * DIM + h * HD;
    const float4* kw4p = (const float4*)(knw + h * HD);

    for (int idx = tid; idx < 80 * 32; idx += 256) {
        const int r = idx >> 5, c = idx & 31;
        const int gr = qb - WIN + r;
        if (gr >= 0) {
            const float f = rsk[b * SEQ + gr];
            float4 kv = h4_to_f4(((const uint2*)(kbase + (size_t)gr * NQKV))[c]);
            float4 w4 = kw4p[c];
            kv.x *= f * w4.x; kv.y *= f * w4.y; kv.z *= f * w4.z; kv.w *= f * w4.w;
            ((float4*)(ks + r * 132))[c] = kv;
            ((float4*)(vs + r * 132))[c] = h4_to_f4(((const uint2*)(vbase + (size_t)gr * NQKV))[c]);
        }
    }
    __syncthreads();

    const float scale = 0.08838834764831845f;   // 1/sqrt(128)
    const float slope = exp2f(-(float)h);       // ALiBi slope, H=8
    const float4 qw4 = ((const float4*)(qnw + h * HD))[lane];

#pragma unroll 1
    for (int it = 0; it < 8; it++) {
        const int t = qb + it * 8 + wid;
        float4 q = h4_to_f4(((const uint2*)(qkvh + (size_t)(b * SEQ + t) * NQKV + h * HD))[lane]);
        const float qf = rsq[b * SEQ + t] * scale;
        q.x *= qf * qw4.x; q.y *= qf * qw4.y; q.z *= qf * qw4.z; q.w *= qf * qw4.w;

        float sc[WIN + 1];
        float mx = -1e30f;
#pragma unroll
        for (int jj = 0; jj <= WIN; jj++) {
            const int j = t - WIN + jj;
            float s = -1e30f;
            if (j >= 0) {
                const int sr = j - qb + WIN;
                const float4 k4 = *(const float4*)(ks + sr * 132 + lane * 4);
                float d = q.x*k4.x + q.y*k4.y + q.z*k4.z + q.w*k4.w;
#pragma unroll
                for (int o = 16; o; o >>= 1) d += __shfl_xor_sync(0xFFFFFFFFu, d, o);
                s = d + slope * (float)(j - t);
            }
            sc[jj] = s;
            mx = fmaxf(mx, s);
        }
        float l = 0.0f;
#pragma unroll
        for (int jj = 0; jj <= WIN; jj++) {
            float e = __expf(sc[jj] - mx);
            sc[jj] = e;
            l += e;
        }
        const float inv = 1.0f / l;

        float4 acc = {0.f, 0.f, 0.f, 0.f};
#pragma unroll
        for (int jj = 0; jj <= WIN; jj++) {
            const int j = t - WIN + jj;
            if (j >= 0) {
                const int sr = j - qb + WIN;
                const float4 v4 = *(const float4*)(vs + sr * 132 + lane * 4);
                const float p = sc[jj] * inv;
                acc.x = fmaf(p, v4.x, acc.x);
                acc.y = fmaf(p, v4.y, acc.y);
                acc.z = fmaf(p, v4.z, acc.z);
                acc.w = fmaf(p, v4.w, acc.w);
            }
        }

        const size_t off = (size_t)(b * SEQ + t) * DIM + h * HD + lane * 4;
        __half2 H0; H0.x = __float2half_rn(acc.x); H0.y = __float2half_rn(acc.y);
        __half2 H1; H1.x = __float2half_rn(acc.z); H1.y = __float2half_rn(acc.w);
        ((__half2*)(yh + off))[0] = H0;
        ((__half2*)(yh + off))[1] = H1;
    }
}

// ---------------- launch ----------------
extern "C" void kernel_launch(void* const* d_in, const int* in_sizes, int n_in,
                              void* d_out, int out_size)
{
    const float* x   = (const float*)d_in[0];
    const float* wq  = (const float*)d_in[1];
    const float* wk  = (const float*)d_in[2];
    const float* wv  = (const float*)d_in[3];
    const float* wo  = (const float*)d_in[4];
    const float* qnw = (const float*)d_in[5];
    const float* knw = (const float*)d_in[6];
    float* out       = (float*)d_out;

    __half *wT, *xh, *qkvh, *yh;
    float *ssp, *rsq, *rsk;
    cudaGetSymbolAddress((void**)&wT,   g_wT);
    cudaGetSymbolAddress((void**)&xh,   g_xh);
    cudaGetSymbolAddress((void**)&qkvh, g_qkvh);
    cudaGetSymbolAddress((void**)&yh,   g_yh);
    cudaGetSymbolAddress((void**)&ssp,  g_ssp);
    cudaGetSymbolAddress((void**)&rsq,  g_rsq);
    cudaGetSymbolAddress((void**)&rsk,  g_rsk);

    cudaFuncSetAttribute(gemm_f16<0>, cudaFuncAttributeMaxDynamicSharedMemorySize, GSMEM);
    cudaFuncSetAttribute(gemm_f16<1>, cudaFuncAttributeMaxDynamicSharedMemorySize, GSMEM);
    cudaFuncSetAttribute(attn_kernel, cudaFuncAttributeMaxDynamicSharedMemorySize, ASMEM);

    // 1) prep: weights transpose -> fp16 [n][k] (z<4) + x -> fp16 (z>=4)
    dim3 pgrid(32, 32, 12), pblk(32, 8);
    prep_kernel<<<pgrid, pblk>>>(x, wq, wk, wv, wo, wT, xh);

    // 2) fused QKV projection -> fp16 + ss partials
    dim3 qkvgrid(NQKV/128, MR/128);
    gemm_f16<1><<<qkvgrid, 256, GSMEM>>>(xh, wT, qkvh, NQKV, ssp);

    // 3) combine partials -> rsqrt factors
    rsfact_kernel<<<MR*2/256, 256>>>(ssp, rsq, rsk);

    // 4) banded attention with fused norm -> y fp16
    dim3 agrid(SEQ/64, NH, BATCH);
    attn_kernel<<<agrid, 256, ASMEM>>>(qkvh, rsq, rsk, qnw, knw, yh);

    // 5) output projection -> fp32 out
    dim3 ogrid(DIM/128, MR/128);
    gemm_f16<0><<<ogrid, 256, GSMEM>>>(yh, wT + (size_t)3072*DIM, out, DIM, nullptr);
}

// round 14
// speedup vs baseline: 1.2369x; 1.1171x over previous
#include <cuda_runtime.h>
#include <cuda_fp16.h>
#include <math.h>
#include <stdint.h>

// ---------------- problem constants ----------------
#define BATCH 4
#define SEQ   2048
#define DIM   1024
#define NH    8
#define HD    128
#define WIN   16
#define EPSV  1e-6f
#define MR    (BATCH*SEQ)   // 8192
#define NQKV  3072
#define NW    4096

// ---------------- device scratch ----------------
__device__ __align__(16) __half g_wT[NW*DIM];
__device__ __align__(16) __half g_xh[MR*DIM];
__device__ __align__(16) __half g_qkvh[MR*NQKV];
__device__ __align__(16) __half g_yh[MR*DIM];
__device__ __align__(16) float  g_ssp[MR*16];
__device__ __align__(16) float  g_rsq[MR];
__device__ __align__(16) float  g_rsk[MR];

// ---------------- PTX helpers ----------------
__device__ __forceinline__ uint32_t smem_u32(const void* p) {
    uint32_t a;
    asm("{ .reg .u64 t; cvta.to.shared.u64 t, %1; cvt.u32.u64 %0, t; }" : "=r"(a) : "l"(p));
    return a;
}
__device__ __forceinline__ void cp16(uint32_t d, const void* s) {
    asm volatile("cp.async.cg.shared.global [%0], [%1], 16;" :: "r"(d), "l"(s));
}
__device__ __forceinline__ void cp_commit() { asm volatile("cp.async.commit_group;" ::: "memory"); }
__device__ __forceinline__ void cp_wait2()  { asm volatile("cp.async.wait_group 2;" ::: "memory"); }
__device__ __forceinline__ void cp_wait1()  { asm volatile("cp.async.wait_group 1;" ::: "memory"); }
__device__ __forceinline__ void cp_wait0()  { asm volatile("cp.async.wait_group 0;" ::: "memory"); }

__device__ __forceinline__ void ldm_x4(uint32_t* r, uint32_t addr) {
    asm volatile("ldmatrix.sync.aligned.m8n8.x4.shared.b16 {%0,%1,%2,%3}, [%4];"
                 : "=r"(r[0]), "=r"(r[1]), "=r"(r[2]), "=r"(r[3]) : "r"(addr));
}
__device__ __forceinline__ void mma_f16(float* c, const uint32_t* a, const uint32_t* b) {
    asm volatile(
        "mma.sync.aligned.m16n8k16.row.col.f32.f16.f16.f32 "
        "{%0,%1,%2,%3}, {%4,%5,%6,%7}, {%8,%9}, {%0,%1,%2,%3};"
        : "+f"(c[0]), "+f"(c[1]), "+f"(c[2]), "+f"(c[3])
        : "r"(a[0]), "r"(a[1]), "r"(a[2]), "r"(a[3]), "r"(b[0]), "r"(b[1]));
}
__device__ __forceinline__ float4 h4_to_f4(uint2 u) {
    __half2 a = *(__half2*)&u.x, b = *(__half2*)&u.y;
    float2 f0 = __half22float2(a), f1 = __half22float2(b);
    float4 r; r.x = f0.x; r.y = f0.y; r.z = f1.x; r.w = f1.y;
    return r;
}

// ---------------- prep: weights transpose->fp16 (z<4) + x convert (z>=4) ----------------
__global__ __launch_bounds__(256)
void prep_kernel(const float* __restrict__ x,
                 const float* __restrict__ wq, const float* __restrict__ wk,
                 const float* __restrict__ wv, const float* __restrict__ wo,
                 __half* __restrict__ wT, __half* __restrict__ xh)
{
    if (blockIdx.z < 4) {
        __shared__ float t[32][33];
        const float* W = (blockIdx.z == 0) ? wq : (blockIdx.z == 1) ? wk
                        : (blockIdx.z == 2) ? wv : wo;
        __half* out = wT + (size_t)blockIdx.z * DIM * DIM;
        const int c0 = blockIdx.x * 32, r0 = blockIdx.y * 32;
        const int tx = threadIdx.x, ty = threadIdx.y;
#pragma unroll
        for (int j = 0; j < 4; j++)
            t[ty + 8*j][tx] = W[(size_t)(r0 + ty + 8*j) * DIM + c0 + tx];
        __syncthreads();
#pragma unroll
        for (int j = 0; j < 4; j++)
            out[(size_t)(c0 + ty + 8*j) * DIM + (r0 + tx)] = __float2half_rn(t[tx][ty + 8*j]);
    } else {
        const int tid = threadIdx.y * 32 + threadIdx.x;
        const int blocklin = (blockIdx.z - 4) * 1024 + blockIdx.y * 32 + blockIdx.x;
        const int i = blocklin * 256 + tid;
        float4 v = ((const float4*)x)[i];
        __half2 H0; H0.x = __float2half_rn(v.x); H0.y = __float2half_rn(v.y);
        __half2 H1; H1.x = __float2half_rn(v.z); H1.y = __float2half_rn(v.w);
        ((__half2*)xh)[2*i]   = H0;
        ((__half2*)xh)[2*i+1] = H1;
    }
}

// ---------------- fp16 warp-MMA GEMM (R9 config, ss-fused epilogue) ----------------
#define TILEB  8192
#define STAGEB (2*TILEB)
#define GSMEM  (4*STAGEB)        // 65536

__device__ __forceinline__ uint32_t swz_addr(uint32_t tile, int row, int chunk) {
    return tile + row * 64 + (((uint32_t)(chunk ^ ((row >> 1) & 3))) << 4);
}
__device__ __forceinline__ void ld_tile(uint32_t sdst, const __half* g,
                                        int grow0, int k0, int lrow, int lc0)
{
    const __half* src = g + (size_t)(grow0 + lrow) * DIM + k0 + lc0 * 8;
    cp16(swz_addr(sdst, lrow, lc0),     src);
    cp16(swz_addr(sdst, lrow, lc0 + 1), src + 8);
}

template<int OUT16>
__global__ __launch_bounds__(256, 2)
void gemm_f16(const __half* __restrict__ a, const __half* __restrict__ b,
              void* __restrict__ Cv, int ldc, float* __restrict__ ssp)
{
    extern __shared__ char smem[];
    const uint32_t sbase = smem_u32(smem);
    const int tid  = threadIdx.x;
    const int lane = tid & 31;
    const int wid  = tid >> 5;
    const int wm   = wid >> 1;
    const int wn   = wid & 1;
    const int m0 = blockIdx.y * 128;
    const int n0 = blockIdx.x * 128;

    const int lrow = tid >> 1;
    const int lc0  = (tid & 1) * 2;

    int arow[2], browx[4];
#pragma unroll
    for (int mt = 0; mt < 2; mt++) arow[mt] = wm * 32 + mt * 16 + (lane & 15);
#pragma unroll
    for (int p = 0; p < 4; p++)
        browx[p] = wn * 64 + p * 16 + ((lane >> 4) << 3) + (lane & 7);
    const int ac = lane >> 4;
    const int bc = (lane >> 3) & 1;

    float acc[2][8][4];
#pragma unroll
    for (int mt = 0; mt < 2; mt++)
#pragma unroll
        for (int nt = 0; nt < 8; nt++)
#pragma unroll
            for (int q = 0; q < 4; q++) acc[mt][nt][q] = 0.0f;

#pragma unroll
    for (int s = 0; s < 3; s++) {
        const uint32_t st = sbase + s * STAGEB;
        const int k0 = s * 32;
        ld_tile(st,         a, m0, k0, lrow, lc0);
        ld_tile(st + TILEB, b, n0, k0, lrow, lc0);
        cp_commit();
    }

    const int NIT = DIM / 32;
    for (int i = 0; i < NIT; i++) {
        if (i < NIT - 2)      cp_wait2();
        else if (i == NIT-2)  cp_wait1();
        else                  cp_wait0();
        __syncthreads();

        if (i + 3 < NIT) {
            const uint32_t st = sbase + ((i + 3) & 3) * STAGEB;
            const int k0 = (i + 3) * 32;
            ld_tile(st,         a, m0, k0, lrow, lc0);
            ld_tile(st + TILEB, b, n0, k0, lrow, lc0);
            cp_commit();
        }

        const uint32_t st = sbase + (i & 3) * STAGEB;
        const uint32_t sA = st;
        const uint32_t sB = st + TILEB;

#pragma unroll
        for (int kh = 0; kh < 2; kh++) {
            uint32_t fB[4][4], fA[2][4];
#pragma unroll
            for (int p = 0; p < 4; p++)
                ldm_x4(fB[p], swz_addr(sB, browx[p], kh * 2 + bc));
#pragma unroll
            for (int mt = 0; mt < 2; mt++)
                ldm_x4(fA[mt], swz_addr(sA, arow[mt], kh * 2 + ac));
#pragma unroll
            for (int mt = 0; mt < 2; mt++)
#pragma unroll
                for (int p = 0; p < 4; p++) {
                    mma_f16(acc[mt][p*2],     fA[mt], &fB[p][0]);
                    mma_f16(acc[mt][p*2 + 1], fA[mt], &fB[p][2]);
                }
        }
    }

    const int erow = lane >> 2;
    const int ecol = (lane & 3) * 2;
#pragma unroll
    for (int mt = 0; mt < 2; mt++) {
#pragma unroll
        for (int nt = 0; nt < 8; nt++) {
            const int r0 = m0 + wm * 32 + mt * 16 + erow;
            const int c0 = n0 + wn * 64 + nt * 8 + ecol;
            if (OUT16) {
                __half* C = (__half*)Cv;
                __half2 h0; h0.x = __float2half_rn(acc[mt][nt][0]); h0.y = __float2half_rn(acc[mt][nt][1]);
                __half2 h1; h1.x = __float2half_rn(acc[mt][nt][2]); h1.y = __float2half_rn(acc[mt][nt][3]);
                *(__half2*)(C + (size_t)r0 * ldc + c0)       = h0;
                *(__half2*)(C + (size_t)(r0 + 8) * ldc + c0) = h1;
            } else {
                float* C = (float*)Cv;
                float2 v0 = {acc[mt][nt][0], acc[mt][nt][1]};
                float2 v1 = {acc[mt][nt][2], acc[mt][nt][3]};
                *(float2*)(C + (size_t)r0 * ldc + c0)       = v0;
                *(float2*)(C + (size_t)(r0 + 8) * ldc + c0) = v1;
            }
        }
    }

    if (OUT16) {
        if (blockIdx.x < 16) {
            float* ssbuf = (float*)smem;
            __syncthreads();
#pragma unroll
            for (int mt = 0; mt < 2; mt++) {
                float p0 = 0.0f, p1 = 0.0f;
#pragma unroll
                for (int nt = 0; nt < 8; nt++) {
                    p0 += acc[mt][nt][0]*acc[mt][nt][0] + acc[mt][nt][1]*acc[mt][nt][1];
                    p1 += acc[mt][nt][2]*acc[mt][nt][2] + acc[mt][nt][3]*acc[mt][nt][3];
                }
                p0 += __shfl_xor_sync(0xFFFFFFFFu, p0, 1);
                p0 += __shfl_xor_sync(0xFFFFFFFFu, p0, 2);
                p1 += __shfl_xor_sync(0xFFFFFFFFu, p1, 1);
                p1 += __shfl_xor_sync(0xFFFFFFFFu, p1, 2);
                if ((lane & 3) == 0) {
                    const int rloc = wm * 32 + mt * 16 + erow;
                    ssbuf[wn * 128 + rloc]     = p0;
                    ssbuf[wn * 128 + rloc + 8] = p1;
                }
            }
            __syncthreads();
            if (tid < 128) {
                float s = ssbuf[tid] + ssbuf[128 + tid];
                ssp[(size_t)(m0 + tid) * 16 + blockIdx.x] = s;
            }
        }
    }
}

// ---------------- combine ss partials -> rsqrt factors ----------------
__global__ __launch_bounds__(256)
void rsfact_kernel(const float* __restrict__ ssp, float* __restrict__ rsq,
                   float* __restrict__ rsk)
{
    const int idx = blockIdx.x * 256 + threadIdx.x;
    const int row = idx >> 1;
    const int slice = idx & 1;
    const float4* p = (const float4*)(ssp + (size_t)row * 16 + slice * 8);
    float4 a = p[0], b = p[1];
    float s = a.x + a.y + a.z + a.w + b.x + b.y + b.z + b.w;
    float rs = rsqrtf(s * (1.0f / DIM) + EPSV);
    (slice == 0 ? rsq : rsk)[row] = rs;
}

// ---------------- banded attention: fp16 smem staging (raw bits), norm folded ----------------
// smem: k 80x136 halves, v 80x136 halves, rk 80 floats
#define KROW 136
#define ASMEM (2 * 80 * KROW * 2 + 80 * 4 + 16)

__global__ __launch_bounds__(256)
void attn_kernel(const __half* __restrict__ qkvh, const float* __restrict__ rsq,
                 const float* __restrict__ rsk, const float* __restrict__ qnw,
                 const float* __restrict__ knw, __half* __restrict__ yh)
{
    extern __shared__ char smraw[];
    __half* ks = (__half*)smraw;
    __half* vs = ks + 80 * KROW;
    float*  rk = (float*)(vs + 80 * KROW);
    const int tid  = threadIdx.x;
    const int lane = tid & 31;
    const int wid  = tid >> 5;
    const int qb = blockIdx.x * 64;
    const int h  = blockIdx.y;
    const int b  = blockIdx.z;

    const __half* kbase = qkvh + (size_t)(b * SEQ) * NQKV + DIM     + h * HD;
    const __half* vbase = qkvh + (size_t)(b * SEQ) * NQKV + 2 * DIM + h * HD;

    // raw bit-copy staging: 80 rows x 16 uint4 chunks each for k and v
    for (int idx = tid; idx < 80 * 16; idx += 256) {
        const int r = idx >> 4, c = idx & 15;
        const int gr = qb - WIN + r;
        if (gr >= 0) {
            ((uint4*)(ks + r * KROW))[c] = ((const uint4*)(kbase + (size_t)gr * NQKV))[c];
            ((uint4*)(vs + r * KROW))[c] = ((const uint4*)(vbase + (size_t)gr * NQKV))[c];
        }
    }
    if (tid < 80) {
        const int gr = qb - WIN + tid;
        rk[tid] = (gr >= 0) ? rsk[b * SEQ + gr] : 0.0f;
    }
    __syncthreads();

    const float scale = 0.08838834764831845f;   // 1/sqrt(128)
    const float slope = exp2f(-(float)h);       // ALiBi slope, H=8
    const float4 qw4 = ((const float4*)(qnw + h * HD))[lane];
    const float4 kw4 = ((const float4*)(knw + h * HD))[lane];

#pragma unroll 1
    for (int it = 0; it < 8; it++) {
        const int t = qb + it * 8 + wid;
        float4 q = h4_to_f4(((const uint2*)(qkvh + (size_t)(b * SEQ + t) * NQKV + h * HD))[lane]);
        const float qf = rsq[b * SEQ + t] * scale;
        // fold qnw, knw, rsq, scale into q; rsk applied post-dot
        q.x *= qf * qw4.x * kw4.x;
        q.y *= qf * qw4.y * kw4.y;
        q.z *= qf * qw4.z * kw4.z;
        q.w *= qf * qw4.w * kw4.w;

        float sc[WIN + 1];
        float mx = -1e30f;
#pragma unroll
        for (int jj = 0; jj <= WIN; jj++) {
            const int j = t - WIN + jj;
            float s = -1e30f;
            if (j >= 0) {
                const int sr = j - qb + WIN;
                const float4 k4 = h4_to_f4(((const uint2*)(ks + sr * KROW))[lane]);
                float d = q.x*k4.x + q.y*k4.y + q.z*k4.z + q.w*k4.w;
#pragma unroll
                for (int o = 16; o; o >>= 1) d += __shfl_xor_sync(0xFFFFFFFFu, d, o);
                s = d * rk[sr] + slope * (float)(j - t);
            }
            sc[jj] = s;
            mx = fmaxf(mx, s);
        }
        float l = 0.0f;
#pragma unroll
        for (int jj = 0; jj <= WIN; jj++) {
            float e = __expf(sc[jj] - mx);
            sc[jj] = e;
            l += e;
        }
        const float inv = 1.0f / l;

        float4 acc = {0.f, 0.f, 0.f, 0.f};
#pragma unroll
        for (int jj = 0; jj <= WIN; jj++) {
            const int j = t - WIN + jj;
            if (j >= 0) {
                const int sr = j - qb + WIN;
                const float4 v4 = h4_to_f4(((const uint2*)(vs + sr * KROW))[lane]);
                const float p = sc[jj] * inv;
                acc.x = fmaf(p, v4.x, acc.x);
                acc.y = fmaf(p, v4.y, acc.y);
                acc.z = fmaf(p, v4.z, acc.z);
                acc.w = fmaf(p, v4.w, acc.w);
            }
        }

        const size_t off = (size_t)(b * SEQ + t) * DIM + h * HD + lane * 4;
        __half2 H0; H0.x = __float2half_rn(acc.x); H0.y = __float2half_rn(acc.y);
        __half2 H1; H1.x = __float2half_rn(acc.z); H1.y = __float2half_rn(acc.w);
        ((__half2*)(yh + off))[0] = H0;
        ((__half2*)(yh + off))[1] = H1;
    }
}

// ---------------- launch ----------------
extern "C" void kernel_launch(void* const* d_in, const int* in_sizes, int n_in,
                              void* d_out, int out_size)
{
    const float* x   = (const float*)d_in[0];
    const float* wq  = (const float*)d_in[1];
    const float* wk  = (const float*)d_in[2];
    const float* wv  = (const float*)d_in[3];
    const float* wo  = (const float*)d_in[4];
    const float* qnw = (const float*)d_in[5];
    const float* knw = (const float*)d_in[6];
    float* out       = (float*)d_out;

    __half *wT, *xh, *qkvh, *yh;
    float *ssp, *rsq, *rsk;
    cudaGetSymbolAddress((void**)&wT,   g_wT);
    cudaGetSymbolAddress((void**)&xh,   g_xh);
    cudaGetSymbolAddress((void**)&qkvh, g_qkvh);
    cudaGetSymbolAddress((void**)&yh,   g_yh);
    cudaGetSymbolAddress((void**)&ssp,  g_ssp);
    cudaGetSymbolAddress((void**)&rsq,  g_rsq);
    cudaGetSymbolAddress((void**)&rsk,  g_rsk);

    cudaFuncSetAttribute(gemm_f16<0>, cudaFuncAttributeMaxDynamicSharedMemorySize, GSMEM);
    cudaFuncSetAttribute(gemm_f16<1>, cudaFuncAttributeMaxDynamicSharedMemorySize, GSMEM);
    cudaFuncSetAttribute(attn_kernel, cudaFuncAttributeMaxDynamicSharedMemorySize, ASMEM);

    // 1) prep
    dim3 pgrid(32, 32, 12), pblk(32, 8);
    prep_kernel<<<pgrid, pblk>>>(x, wq, wk, wv, wo, wT, xh);

    // 2) fused QKV projection -> fp16 + ss partials
    dim3 qkvgrid(NQKV/128, MR/128);
    gemm_f16<1><<<qkvgrid, 256, GSMEM>>>(xh, wT, qkvh, NQKV, ssp);

    // 3) rsqrt factors
    rsfact_kernel<<<MR*2/256, 256>>>(ssp, rsq, rsk);

    // 4) banded attention (fp16 staging, folded norms) -> y fp16
    dim3 agrid(SEQ/64, NH, BATCH);
    attn_kernel<<<agrid, 256, ASMEM>>>(qkvh, rsq, rsk, qnw, knw, yh);

    // 5) output projection -> fp32 out
    dim3 ogrid(DIM/128, MR/128);
    gemm_f16<0><<<ogrid, 256, GSMEM>>>(yh, wT + (size_t)3072*DIM, out, DIM, nullptr);
}

// round 15
// speedup vs baseline: 1.3303x; 1.0756x over previous
#include <cuda_runtime.h>
#include <cuda_fp16.h>
#include <math.h>
#include <stdint.h>

// ---------------- problem constants ----------------
#define BATCH 4
#define SEQ   2048
#define DIM   1024
#define NH    8
#define HD    128
#define WIN   16
#define EPSV  1e-6f
#define MR    (BATCH*SEQ)   // 8192
#define NQKV  3072
#define NW    4096

// ---------------- device scratch ----------------
__device__ __align__(16) __half g_wT[NW*DIM];
__device__ __align__(16) __half g_xh[MR*DIM];
__device__ __align__(16) __half g_qkvh[MR*NQKV];
__device__ __align__(16) __half g_yh[MR*DIM];
__device__ __align__(16) float  g_ssp[MR*16];
__device__ __align__(16) float  g_rsq[MR];
__device__ __align__(16) float  g_rsk[MR];

// ---------------- PTX helpers ----------------
__device__ __forceinline__ uint32_t smem_u32(const void* p) {
    uint32_t a;
    asm("{ .reg .u64 t; cvta.to.shared.u64 t, %1; cvt.u32.u64 %0, t; }" : "=r"(a) : "l"(p));
    return a;
}
__device__ __forceinline__ void cp16(uint32_t d, const void* s) {
    asm volatile("cp.async.cg.shared.global [%0], [%1], 16;" :: "r"(d), "l"(s));
}
__device__ __forceinline__ void cp_commit() { asm volatile("cp.async.commit_group;" ::: "memory"); }
__device__ __forceinline__ void cp_wait2()  { asm volatile("cp.async.wait_group 2;" ::: "memory"); }
__device__ __forceinline__ void cp_wait1()  { asm volatile("cp.async.wait_group 1;" ::: "memory"); }
__device__ __forceinline__ void cp_wait0()  { asm volatile("cp.async.wait_group 0;" ::: "memory"); }

__device__ __forceinline__ void ldm_x4(uint32_t* r, uint32_t addr) {
    asm volatile("ldmatrix.sync.aligned.m8n8.x4.shared.b16 {%0,%1,%2,%3}, [%4];"
                 : "=r"(r[0]), "=r"(r[1]), "=r"(r[2]), "=r"(r[3]) : "r"(addr));
}
__device__ __forceinline__ void mma_f16(float* c, const uint32_t* a, const uint32_t* b) {
    asm volatile(
        "mma.sync.aligned.m16n8k16.row.col.f32.f16.f16.f32 "
        "{%0,%1,%2,%3}, {%4,%5,%6,%7}, {%8,%9}, {%0,%1,%2,%3};"
        : "+f"(c[0]), "+f"(c[1]), "+f"(c[2]), "+f"(c[3])
        : "r"(a[0]), "r"(a[1]), "r"(a[2]), "r"(a[3]), "r"(b[0]), "r"(b[1]));
}

// ---------------- prep: weights transpose->fp16 (z<4) + x convert (z>=4) ----------------
__global__ __launch_bounds__(256)
void prep_kernel(const float* __restrict__ x,
                 const float* __restrict__ wq, const float* __restrict__ wk,
                 const float* __restrict__ wv, const float* __restrict__ wo,
                 __half* __restrict__ wT, __half* __restrict__ xh)
{
    if (blockIdx.z < 4) {
        __shared__ float t[32][33];
        const float* W = (blockIdx.z == 0) ? wq : (blockIdx.z == 1) ? wk
                        : (blockIdx.z == 2) ? wv : wo;
        __half* out = wT + (size_t)blockIdx.z * DIM * DIM;
        const int c0 = blockIdx.x * 32, r0 = blockIdx.y * 32;
        const int tx = threadIdx.x, ty = threadIdx.y;
#pragma unroll
        for (int j = 0; j < 4; j++)
            t[ty + 8*j][tx] = W[(size_t)(r0 + ty + 8*j) * DIM + c0 + tx];
        __syncthreads();
#pragma unroll
        for (int j = 0; j < 4; j++)
            out[(size_t)(c0 + ty + 8*j) * DIM + (r0 + tx)] = __float2half_rn(t[tx][ty + 8*j]);
    } else {
        const int tid = threadIdx.y * 32 + threadIdx.x;
        const int blocklin = (blockIdx.z - 4) * 1024 + blockIdx.y * 32 + blockIdx.x;
        const int i = blocklin * 256 + tid;
        float4 v = ((const float4*)x)[i];
        __half2 H0; H0.x = __float2half_rn(v.x); H0.y = __float2half_rn(v.y);
        __half2 H1; H1.x = __float2half_rn(v.z); H1.y = __float2half_rn(v.w);
        ((__half2*)xh)[2*i]   = H0;
        ((__half2*)xh)[2*i+1] = H1;
    }
}

// ---------------- fp16 warp-MMA GEMM (R9 config, ss-fused epilogue) ----------------
#define TILEB  8192
#define STAGEB (2*TILEB)
#define GSMEM  (4*STAGEB)

__device__ __forceinline__ uint32_t swz_addr(uint32_t tile, int row, int chunk) {
    return tile + row * 64 + (((uint32_t)(chunk ^ ((row >> 1) & 3))) << 4);
}
__device__ __forceinline__ void ld_tile(uint32_t sdst, const __half* g,
                                        int grow0, int k0, int lrow, int lc0)
{
    const __half* src = g + (size_t)(grow0 + lrow) * DIM + k0 + lc0 * 8;
    cp16(swz_addr(sdst, lrow, lc0),     src);
    cp16(swz_addr(sdst, lrow, lc0 + 1), src + 8);
}

template<int OUT16>
__global__ __launch_bounds__(256, 2)
void gemm_f16(const __half* __restrict__ a, const __half* __restrict__ b,
              void* __restrict__ Cv, int ldc, float* __restrict__ ssp)
{
    extern __shared__ char smem[];
    const uint32_t sbase = smem_u32(smem);
    const int tid  = threadIdx.x;
    const int lane = tid & 31;
    const int wid  = tid >> 5;
    const int wm   = wid >> 1;
    const int wn   = wid & 1;
    const int m0 = blockIdx.y * 128;
    const int n0 = blockIdx.x * 128;

    const int lrow = tid >> 1;
    const int lc0  = (tid & 1) * 2;

    int arow[2], browx[4];
#pragma unroll
    for (int mt = 0; mt < 2; mt++) arow[mt] = wm * 32 + mt * 16 + (lane & 15);
#pragma unroll
    for (int p = 0; p < 4; p++)
        browx[p] = wn * 64 + p * 16 + ((lane >> 4) << 3) + (lane & 7);
    const int ac = lane >> 4;
    const int bc = (lane >> 3) & 1;

    float acc[2][8][4];
#pragma unroll
    for (int mt = 0; mt < 2; mt++)
#pragma unroll
        for (int nt = 0; nt < 8; nt++)
#pragma unroll
            for (int q = 0; q < 4; q++) acc[mt][nt][q] = 0.0f;

#pragma unroll
    for (int s = 0; s < 3; s++) {
        const uint32_t st = sbase + s * STAGEB;
        const int k0 = s * 32;
        ld_tile(st,         a, m0, k0, lrow, lc0);
        ld_tile(st + TILEB, b, n0, k0, lrow, lc0);
        cp_commit();
    }

    const int NIT = DIM / 32;
    for (int i = 0; i < NIT; i++) {
        if (i < NIT - 2)      cp_wait2();
        else if (i == NIT-2)  cp_wait1();
        else                  cp_wait0();
        __syncthreads();

        if (i + 3 < NIT) {
            const uint32_t st = sbase + ((i + 3) & 3) * STAGEB;
            const int k0 = (i + 3) * 32;
            ld_tile(st,         a, m0, k0, lrow, lc0);
            ld_tile(st + TILEB, b, n0, k0, lrow, lc0);
            cp_commit();
        }

        const uint32_t st = sbase + (i & 3) * STAGEB;
        const uint32_t sA = st;
        const uint32_t sB = st + TILEB;

#pragma unroll
        for (int kh = 0; kh < 2; kh++) {
            uint32_t fB[4][4], fA[2][4];
#pragma unroll
            for (int p = 0; p < 4; p++)
                ldm_x4(fB[p], swz_addr(sB, browx[p], kh * 2 + bc));
#pragma unroll
            for (int mt = 0; mt < 2; mt++)
                ldm_x4(fA[mt], swz_addr(sA, arow[mt], kh * 2 + ac));
#pragma unroll
            for (int mt = 0; mt < 2; mt++)
#pragma unroll
                for (int p = 0; p < 4; p++) {
                    mma_f16(acc[mt][p*2],     fA[mt], &fB[p][0]);
                    mma_f16(acc[mt][p*2 + 1], fA[mt], &fB[p][2]);
                }
        }
    }

    const int erow = lane >> 2;
    const int ecol = (lane & 3) * 2;
#pragma unroll
    for (int mt = 0; mt < 2; mt++) {
#pragma unroll
        for (int nt = 0; nt < 8; nt++) {
            const int r0 = m0 + wm * 32 + mt * 16 + erow;
            const int c0 = n0 + wn * 64 + nt * 8 + ecol;
            if (OUT16) {
                __half* C = (__half*)Cv;
                __half2 h0; h0.x = __float2half_rn(acc[mt][nt][0]); h0.y = __float2half_rn(acc[mt][nt][1]);
                __half2 h1; h1.x = __float2half_rn(acc[mt][nt][2]); h1.y = __float2half_rn(acc[mt][nt][3]);
                *(__half2*)(C + (size_t)r0 * ldc + c0)       = h0;
                *(__half2*)(C + (size_t)(r0 + 8) * ldc + c0) = h1;
            } else {
                float* C = (float*)Cv;
                float2 v0 = {acc[mt][nt][0], acc[mt][nt][1]};
                float2 v1 = {acc[mt][nt][2], acc[mt][nt][3]};
                *(float2*)(C + (size_t)r0 * ldc + c0)       = v0;
                *(float2*)(C + (size_t)(r0 + 8) * ldc + c0) = v1;
            }
        }
    }

    if (OUT16) {
        if (blockIdx.x < 16) {
            float* ssbuf = (float*)smem;
            __syncthreads();
#pragma unroll
            for (int mt = 0; mt < 2; mt++) {
                float p0 = 0.0f, p1 = 0.0f;
#pragma unroll
                for (int nt = 0; nt < 8; nt++) {
                    p0 += acc[mt][nt][0]*acc[mt][nt][0] + acc[mt][nt][1]*acc[mt][nt][1];
                    p1 += acc[mt][nt][2]*acc[mt][nt][2] + acc[mt][nt][3]*acc[mt][nt][3];
                }
                p0 += __shfl_xor_sync(0xFFFFFFFFu, p0, 1);
                p0 += __shfl_xor_sync(0xFFFFFFFFu, p0, 2);
                p1 += __shfl_xor_sync(0xFFFFFFFFu, p1, 1);
                p1 += __shfl_xor_sync(0xFFFFFFFFu, p1, 2);
                if ((lane & 3) == 0) {
                    const int rloc = wm * 32 + mt * 16 + erow;
                    ssbuf[wn * 128 + rloc]     = p0;
                    ssbuf[wn * 128 + rloc + 8] = p1;
                }
            }
            __syncthreads();
            if (tid < 128) {
                float s = ssbuf[tid] + ssbuf[128 + tid];
                ssp[(size_t)(m0 + tid) * 16 + blockIdx.x] = s;
            }
        }
    }
}

// ---------------- combine ss partials -> rsqrt factors ----------------
__global__ __launch_bounds__(256)
void rsfact_kernel(const float* __restrict__ ssp, float* __restrict__ rsq,
                   float* __restrict__ rsk)
{
    const int idx = blockIdx.x * 256 + threadIdx.x;
    const int row = idx >> 1;
    const int slice = idx & 1;
    const float4* p = (const float4*)(ssp + (size_t)row * 16 + slice * 8);
    float4 a = p[0], b = p[1];
    float s = a.x + a.y + a.z + a.w + b.x + b.y + b.z + b.w;
    float rs = rsqrtf(s * (1.0f / DIM) + EPSV);
    (slice == 0 ? rsq : rsk)[row] = rs;
}

// ---------------- mma-based banded attention ----------------
// block = (qb=64 queries, h, b), 128 threads (4 warps), warp w: queries r0=w*16..+15,
// keys window cols r0..r0+31 of the 80-key staging window.
#define QROW 136
#define KROW 136
#define VROW 88
#define ASMEM (64*QROW*2 + 80*KROW*2 + 128*VROW*2 + 80*4)

__global__ __launch_bounds__(128, 3)
void attn_kernel(const __half* __restrict__ qkvh, const float* __restrict__ rsq,
                 const float* __restrict__ rsk, const float* __restrict__ qnw,
                 const float* __restrict__ knw, __half* __restrict__ yh)
{
    extern __shared__ char smraw[];
    __half* Qs = (__half*)smraw;             // 64 x 136
    __half* Ks = Qs + 64 * QROW;             // 80 x 136
    __half* VT = Ks + 80 * KROW;             // 128 x 88 (transposed V)
    float*  rk = (float*)(VT + 128 * VROW);  // 80
    const int tid  = threadIdx.x;
    const int lane = tid & 31;
    const int w    = tid >> 5;               // 0..3
    const int qb = blockIdx.x * 64;
    const int h  = blockIdx.y;
    const int b  = blockIdx.z;

    const __half* qbase = qkvh + (size_t)(b * SEQ) * NQKV + h * HD;
    const __half* kbase = qbase + DIM;
    const __half* vbase = qbase + 2 * DIM;

    if (tid < 80) {
        const int gr = qb - WIN + tid;
        rk[tid] = (gr >= 0) ? rsk[b * SEQ + gr] : 0.0f;
    }
    // K staging (raw bits, zero-fill out-of-range)
    for (int idx = tid; idx < 80 * 16; idx += 128) {
        const int r = idx >> 4, c = idx & 15;
        const int gr = qb - WIN + r;
        uint4 u = make_uint4(0u, 0u, 0u, 0u);
        if (gr >= 0) u = ((const uint4*)(kbase + (size_t)gr * NQKV))[c];
        *(uint4*)(Ks + r * KROW + c * 8) = u;
    }
    // Q staging: fold rsq*scale*qnw*knw, round to fp16
    for (int idx = tid; idx < 64 * 16; idx += 128) {
        const int r = idx >> 4, c = idx & 15;
        const int t = qb + r;
        uint4 u = ((const uint4*)(qbase + (size_t)t * NQKV))[c];
        const float qf = rsq[b * SEQ + t] * 0.08838834764831845f;
        const float4 qw0 = ((const float4*)(qnw + h * HD + c * 8))[0];
        const float4 qw1 = ((const float4*)(qnw + h * HD + c * 8))[1];
        const float4 kw0 = ((const float4*)(knw + h * HD + c * 8))[0];
        const float4 kw1 = ((const float4*)(knw + h * HD + c * 8))[1];
        float f[8], g[8];
        const __half2* hp = (const __half2*)&u;
#pragma unroll
        for (int j = 0; j < 4; j++) {
            float2 t2 = __half22float2(hp[j]);
            f[2*j] = t2.x; f[2*j+1] = t2.y;
        }
        g[0]=qw0.x*kw0.x; g[1]=qw0.y*kw0.y; g[2]=qw0.z*kw0.z; g[3]=qw0.w*kw0.w;
        g[4]=qw1.x*kw1.x; g[5]=qw1.y*kw1.y; g[6]=qw1.z*kw1.z; g[7]=qw1.w*kw1.w;
        uint4 out;
        __half2* op = (__half2*)&out;
#pragma unroll
        for (int j = 0; j < 4; j++) {
            __half2 hh;
            hh.x = __float2half_rn(f[2*j]   * qf * g[2*j]);
            hh.y = __float2half_rn(f[2*j+1] * qf * g[2*j+1]);
            op[j] = hh;
        }
        *(uint4*)(Qs + r * QROW + c * 8) = out;
    }
    // V staging transposed: VT[dim][key]
    for (int idx = tid; idx < 80 * 16; idx += 128) {
        const int r = idx >> 4, c = idx & 15;
        const int gr = qb - WIN + r;
        uint4 u = make_uint4(0u, 0u, 0u, 0u);
        if (gr >= 0) u = ((const uint4*)(vbase + (size_t)gr * NQKV))[c];
        const __half* hv = (const __half*)&u;
#pragma unroll
        for (int j = 0; j < 8; j++)
            VT[(c * 8 + j) * VROW + r] = hv[j];
    }
    __syncthreads();

    const uint32_t Qb = smem_u32(Qs);
    const uint32_t Kb = smem_u32(Ks);
    const uint32_t Vb = smem_u32(VT);
    const int r0 = w * 16;

    // ---- S = Q @ K^T : 16x32, 8 k-chunks ----
    float sc[4][4];
#pragma unroll
    for (int t4 = 0; t4 < 4; t4++)
#pragma unroll
        for (int q = 0; q < 4; q++) sc[t4][q] = 0.0f;

    const uint32_t aAddr = Qb + (uint32_t)(r0 + (lane & 15)) * (QROW*2) + (uint32_t)(lane >> 4) * 16;
    const int bc = (lane >> 3) & 1;
    const int brow_off = ((lane >> 4) << 3) + (lane & 7);
#pragma unroll
    for (int kc = 0; kc < 8; kc++) {
        uint32_t fA[4];
        ldm_x4(fA, aAddr + kc * 32);
#pragma unroll
        for (int pg = 0; pg < 2; pg++) {
            uint32_t fB[4];
            const int brow = r0 + pg * 16 + brow_off;
            ldm_x4(fB, Kb + (uint32_t)brow * (KROW*2) + (uint32_t)(kc * 2 + bc) * 16);
            mma_f16(sc[pg*2],     fA, &fB[0]);
            mma_f16(sc[pg*2 + 1], fA, &fB[2]);
        }
    }

    // ---- softmax in fragments ----
    const int crow = lane >> 2;
    const int ccol = (lane & 3) * 2;
    const float slope = exp2f(-(float)h);
    float mx0 = -1e30f, mx1 = -1e30f;
#pragma unroll
    for (int t4 = 0; t4 < 4; t4++) {
#pragma unroll
        for (int q = 0; q < 4; q++) {
            const int colL = t4 * 8 + ccol + (q & 1);
            const int rowL = crow + ((q & 2) ? 8 : 0);
            const int rel = colL - 16 - rowL;
            const bool valid = (rel <= 0) && (rel >= -WIN) && (qb + r0 + colL >= 16);
            float s = valid ? sc[t4][q] * rk[r0 + colL] + slope * (float)rel : -1e30f;
            sc[t4][q] = s;
            if (q & 2) mx1 = fmaxf(mx1, s); else mx0 = fmaxf(mx0, s);
        }
    }
    mx0 = fmaxf(mx0, __shfl_xor_sync(0xFFFFFFFFu, mx0, 1));
    mx0 = fmaxf(mx0, __shfl_xor_sync(0xFFFFFFFFu, mx0, 2));
    mx1 = fmaxf(mx1, __shfl_xor_sync(0xFFFFFFFFu, mx1, 1));
    mx1 = fmaxf(mx1, __shfl_xor_sync(0xFFFFFFFFu, mx1, 2));

    float l0 = 0.0f, l1 = 0.0f;
#pragma unroll
    for (int t4 = 0; t4 < 4; t4++) {
#pragma unroll
        for (int q = 0; q < 4; q++) {
            float e = __expf(sc[t4][q] - ((q & 2) ? mx1 : mx0));
            sc[t4][q] = e;
            if (q & 2) l1 += e; else l0 += e;
        }
    }
    l0 += __shfl_xor_sync(0xFFFFFFFFu, l0, 1);
    l0 += __shfl_xor_sync(0xFFFFFFFFu, l0, 2);
    l1 += __shfl_xor_sync(0xFFFFFFFFu, l1, 1);
    l1 += __shfl_xor_sync(0xFFFFFFFFu, l1, 2);
    const float inv0 = 1.0f / l0, inv1 = 1.0f / l1;

    // pack P into a-fragments (c-layout -> a-layout identity)
    uint32_t aP[2][4];
#pragma unroll
    for (int kc2 = 0; kc2 < 2; kc2++) {
        const int t0 = kc2 * 2, t1 = t0 + 1;
        __half2 h0, h1, h2v, h3;
        h0.x  = __float2half_rn(sc[t0][0] * inv0); h0.y  = __float2half_rn(sc[t0][1] * inv0);
        h1.x  = __float2half_rn(sc[t0][2] * inv1); h1.y  = __float2half_rn(sc[t0][3] * inv1);
        h2v.x = __float2half_rn(sc[t1][0] * inv0); h2v.y = __float2half_rn(sc[t1][1] * inv0);
        h3.x  = __float2half_rn(sc[t1][2] * inv1); h3.y  = __float2half_rn(sc[t1][3] * inv1);
        aP[kc2][0] = *(uint32_t*)&h0;
        aP[kc2][1] = *(uint32_t*)&h1;
        aP[kc2][2] = *(uint32_t*)&h2v;
        aP[kc2][3] = *(uint32_t*)&h3;
    }

    // ---- O = P @ V : 16x128, 2 k-chunks ----
    float o[16][4];
#pragma unroll
    for (int nt = 0; nt < 16; nt++)
#pragma unroll
        for (int q = 0; q < 4; q++) o[nt][q] = 0.0f;

#pragma unroll
    for (int kc2 = 0; kc2 < 2; kc2++) {
#pragma unroll
        for (int pg = 0; pg < 8; pg++) {
            const int vrow = pg * 16 + brow_off;
            uint32_t fB[4];
            ldm_x4(fB, Vb + (uint32_t)vrow * (VROW*2) + (uint32_t)(r0 + kc2 * 16 + bc * 8) * 2);
            mma_f16(o[pg*2],     aP[kc2], &fB[0]);
            mma_f16(o[pg*2 + 1], aP[kc2], &fB[2]);
        }
    }

    // ---- store y (fp16) ----
    __half* ybase = yh + (size_t)(b * SEQ + qb + r0) * DIM + h * HD;
#pragma unroll
    for (int nt = 0; nt < 16; nt++) {
        const int col = nt * 8 + ccol;
        __half2 h0; h0.x = __float2half_rn(o[nt][0]); h0.y = __float2half_rn(o[nt][1]);
        __half2 h1; h1.x = __float2half_rn(o[nt][2]); h1.y = __float2half_rn(o[nt][3]);
        *(__half2*)(ybase + (size_t)crow * DIM + col)       = h0;
        *(__half2*)(ybase + (size_t)(crow + 8) * DIM + col) = h1;
    }
}

// ---------------- launch ----------------
extern "C" void kernel_launch(void* const* d_in, const int* in_sizes, int n_in,
                              void* d_out, int out_size)
{
    const float* x   = (const float*)d_in[0];
    const float* wq  = (const float*)d_in[1];
    const float* wk  = (const float*)d_in[2];
    const float* wv  = (const float*)d_in[3];
    const float* wo  = (const float*)d_in[4];
    const float* qnw = (const float*)d_in[5];
    const float* knw = (const float*)d_in[6];
    float* out       = (float*)d_out;

    __half *wT, *xh, *qkvh, *yh;
    float *ssp, *rsq, *rsk;
    cudaGetSymbolAddress((void**)&wT,   g_wT);
    cudaGetSymbolAddress((void**)&xh,   g_xh);
    cudaGetSymbolAddress((void**)&qkvh, g_qkvh);
    cudaGetSymbolAddress((void**)&yh,   g_yh);
    cudaGetSymbolAddress((void**)&ssp,  g_ssp);
    cudaGetSymbolAddress((void**)&rsq,  g_rsq);
    cudaGetSymbolAddress((void**)&rsk,  g_rsk);

    cudaFuncSetAttribute(gemm_f16<0>, cudaFuncAttributeMaxDynamicSharedMemorySize, GSMEM);
    cudaFuncSetAttribute(gemm_f16<1>, cudaFuncAttributeMaxDynamicSharedMemorySize, GSMEM);
    cudaFuncSetAttribute(attn_kernel, cudaFuncAttributeMaxDynamicSharedMemorySize, ASMEM);

    // 1) prep
    dim3 pgrid(32, 32, 12), pblk(32, 8);
    prep_kernel<<<pgrid, pblk>>>(x, wq, wk, wv, wo, wT, xh);

    // 2) fused QKV projection -> fp16 + ss partials
    dim3 qkvgrid(NQKV/128, MR/128);
    gemm_f16<1><<<qkvgrid, 256, GSMEM>>>(xh, wT, qkvh, NQKV, ssp);

    // 3) rsqrt factors
    rsfact_kernel<<<MR*2/256, 256>>>(ssp, rsq, rsk);

    // 4) mma-based banded attention -> y fp16
    dim3 agrid(SEQ/64, NH, BATCH);
    attn_kernel<<<agrid, 128, ASMEM>>>(qkvh, rsq, rsk, qnw, knw, yh);

    // 5) output projection -> fp32 out
    dim3 ogrid(DIM/128, MR/128);
    gemm_f16<0><<<ogrid, 256, GSMEM>>>(yh, wT + (size_t)3072*DIM, out, DIM, nullptr);
}

// round 16
// speedup vs baseline: 1.4209x; 1.0681x over previous
#include <cuda_runtime.h>
#include <cuda_fp16.h>
#include <math.h>
#include <stdint.h>

// ---------------- problem constants ----------------
#define BATCH 4
#define SEQ   2048
#define DIM   1024
#define NH    8
#define HD    128
#define WIN   16
#define EPSV  1e-6f
#define MR    (BATCH*SEQ)   // 8192
#define NQKV  3072
#define NW    4096

// ---------------- device scratch ----------------
__device__ __align__(16) __half g_wT[NW*DIM];
__device__ __align__(16) __half g_xh[MR*DIM];
__device__ __align__(16) __half g_qkvh[MR*NQKV];
__device__ __align__(16) __half g_yh[MR*DIM];
__device__ __align__(16) float  g_ssp[MR*16];
__device__ __align__(16) float  g_rsq[MR];
__device__ __align__(16) float  g_rsk[MR];

// ---------------- PTX helpers ----------------
__device__ __forceinline__ uint32_t smem_u32(const void* p) {
    uint32_t a;
    asm("{ .reg .u64 t; cvta.to.shared.u64 t, %1; cvt.u32.u64 %0, t; }" : "=r"(a) : "l"(p));
    return a;
}
__device__ __forceinline__ void cp16(uint32_t d, const void* s) {
    asm volatile("cp.async.cg.shared.global [%0], [%1], 16;" :: "r"(d), "l"(s));
}
__device__ __forceinline__ void cp_commit() { asm volatile("cp.async.commit_group;" ::: "memory"); }
__device__ __forceinline__ void cp_wait2()  { asm volatile("cp.async.wait_group 2;" ::: "memory"); }
__device__ __forceinline__ void cp_wait1()  { asm volatile("cp.async.wait_group 1;" ::: "memory"); }
__device__ __forceinline__ void cp_wait0()  { asm volatile("cp.async.wait_group 0;" ::: "memory"); }

__device__ __forceinline__ void ldm_x4(uint32_t* r, uint32_t addr) {
    asm volatile("ldmatrix.sync.aligned.m8n8.x4.shared.b16 {%0,%1,%2,%3}, [%4];"
                 : "=r"(r[0]), "=r"(r[1]), "=r"(r[2]), "=r"(r[3]) : "r"(addr));
}
__device__ __forceinline__ void ldm_x4_trans(uint32_t* r, uint32_t addr) {
    asm volatile("ldmatrix.sync.aligned.m8n8.x4.trans.shared.b16 {%0,%1,%2,%3}, [%4];"
                 : "=r"(r[0]), "=r"(r[1]), "=r"(r[2]), "=r"(r[3]) : "r"(addr));
}
__device__ __forceinline__ void mma_f16(float* c, const uint32_t* a, const uint32_t* b) {
    asm volatile(
        "mma.sync.aligned.m16n8k16.row.col.f32.f16.f16.f32 "
        "{%0,%1,%2,%3}, {%4,%5,%6,%7}, {%8,%9}, {%0,%1,%2,%3};"
        : "+f"(c[0]), "+f"(c[1]), "+f"(c[2]), "+f"(c[3])
        : "r"(a[0]), "r"(a[1]), "r"(a[2]), "r"(a[3]), "r"(b[0]), "r"(b[1]));
}

// ---------------- prep: weights transpose->fp16 (z<4) + x convert (z>=4) ----------------
__global__ __launch_bounds__(256)
void prep_kernel(const float* __restrict__ x,
                 const float* __restrict__ wq, const float* __restrict__ wk,
                 const float* __restrict__ wv, const float* __restrict__ wo,
                 __half* __restrict__ wT, __half* __restrict__ xh)
{
    if (blockIdx.z < 4) {
        __shared__ float t[32][33];
        const float* W = (blockIdx.z == 0) ? wq : (blockIdx.z == 1) ? wk
                        : (blockIdx.z == 2) ? wv : wo;
        __half* out = wT + (size_t)blockIdx.z * DIM * DIM;
        const int c0 = blockIdx.x * 32, r0 = blockIdx.y * 32;
        const int tx = threadIdx.x, ty = threadIdx.y;
#pragma unroll
        for (int j = 0; j < 4; j++)
            t[ty + 8*j][tx] = W[(size_t)(r0 + ty + 8*j) * DIM + c0 + tx];
        __syncthreads();
#pragma unroll
        for (int j = 0; j < 4; j++)
            out[(size_t)(c0 + ty + 8*j) * DIM + (r0 + tx)] = __float2half_rn(t[tx][ty + 8*j]);
    } else {
        const int tid = threadIdx.y * 32 + threadIdx.x;
        const int blocklin = (blockIdx.z - 4) * 1024 + blockIdx.y * 32 + blockIdx.x;
        const int i = blocklin * 256 + tid;
        float4 v = ((const float4*)x)[i];
        __half2 H0; H0.x = __float2half_rn(v.x); H0.y = __float2half_rn(v.y);
        __half2 H1; H1.x = __float2half_rn(v.z); H1.y = __float2half_rn(v.w);
        ((__half2*)xh)[2*i]   = H0;
        ((__half2*)xh)[2*i+1] = H1;
    }
}

// ---------------- fp16 warp-MMA GEMM (R9 config, ss-fused epilogue) ----------------
#define TILEB  8192
#define STAGEB (2*TILEB)
#define GSMEM  (4*STAGEB)

__device__ __forceinline__ uint32_t swz_addr(uint32_t tile, int row, int chunk) {
    return tile + row * 64 + (((uint32_t)(chunk ^ ((row >> 1) & 3))) << 4);
}
__device__ __forceinline__ void ld_tile(uint32_t sdst, const __half* g,
                                        int grow0, int k0, int lrow, int lc0)
{
    const __half* src = g + (size_t)(grow0 + lrow) * DIM + k0 + lc0 * 8;
    cp16(swz_addr(sdst, lrow, lc0),     src);
    cp16(swz_addr(sdst, lrow, lc0 + 1), src + 8);
}

template<int OUT16>
__global__ __launch_bounds__(256, 2)
void gemm_f16(const __half* __restrict__ a, const __half* __restrict__ b,
              void* __restrict__ Cv, int ldc, float* __restrict__ ssp)
{
    extern __shared__ char smem[];
    const uint32_t sbase = smem_u32(smem);
    const int tid  = threadIdx.x;
    const int lane = tid & 31;
    const int wid  = tid >> 5;
    const int wm   = wid >> 1;
    const int wn   = wid & 1;
    const int m0 = blockIdx.y * 128;
    const int n0 = blockIdx.x * 128;

    const int lrow = tid >> 1;
    const int lc0  = (tid & 1) * 2;

    int arow[2], browx[4];
#pragma unroll
    for (int mt = 0; mt < 2; mt++) arow[mt] = wm * 32 + mt * 16 + (lane & 15);
#pragma unroll
    for (int p = 0; p < 4; p++)
        browx[p] = wn * 64 + p * 16 + ((lane >> 4) << 3) + (lane & 7);
    const int ac = lane >> 4;
    const int bc = (lane >> 3) & 1;

    float acc[2][8][4];
#pragma unroll
    for (int mt = 0; mt < 2; mt++)
#pragma unroll
        for (int nt = 0; nt < 8; nt++)
#pragma unroll
            for (int q = 0; q < 4; q++) acc[mt][nt][q] = 0.0f;

#pragma unroll
    for (int s = 0; s < 3; s++) {
        const uint32_t st = sbase + s * STAGEB;
        const int k0 = s * 32;
        ld_tile(st,         a, m0, k0, lrow, lc0);
        ld_tile(st + TILEB, b, n0, k0, lrow, lc0);
        cp_commit();
    }

    const int NIT = DIM / 32;
    for (int i = 0; i < NIT; i++) {
        if (i < NIT - 2)      cp_wait2();
        else if (i == NIT-2)  cp_wait1();
        else                  cp_wait0();
        __syncthreads();

        if (i + 3 < NIT) {
            const uint32_t st = sbase + ((i + 3) & 3) * STAGEB;
            const int k0 = (i + 3) * 32;
            ld_tile(st,         a, m0, k0, lrow, lc0);
            ld_tile(st + TILEB, b, n0, k0, lrow, lc0);
            cp_commit();
        }

        const uint32_t st = sbase + (i & 3) * STAGEB;
        const uint32_t sA = st;
        const uint32_t sB = st + TILEB;

#pragma unroll
        for (int kh = 0; kh < 2; kh++) {
            uint32_t fB[4][4], fA[2][4];
#pragma unroll
            for (int p = 0; p < 4; p++)
                ldm_x4(fB[p], swz_addr(sB, browx[p], kh * 2 + bc));
#pragma unroll
            for (int mt = 0; mt < 2; mt++)
                ldm_x4(fA[mt], swz_addr(sA, arow[mt], kh * 2 + ac));
#pragma unroll
            for (int mt = 0; mt < 2; mt++)
#pragma unroll
                for (int p = 0; p < 4; p++) {
                    mma_f16(acc[mt][p*2],     fA[mt], &fB[p][0]);
                    mma_f16(acc[mt][p*2 + 1], fA[mt], &fB[p][2]);
                }
        }
    }

    const int erow = lane >> 2;
    const int ecol = (lane & 3) * 2;
#pragma unroll
    for (int mt = 0; mt < 2; mt++) {
#pragma unroll
        for (int nt = 0; nt < 8; nt++) {
            const int r0 = m0 + wm * 32 + mt * 16 + erow;
            const int c0 = n0 + wn * 64 + nt * 8 + ecol;
            if (OUT16) {
                __half* C = (__half*)Cv;
                __half2 h0; h0.x = __float2half_rn(acc[mt][nt][0]); h0.y = __float2half_rn(acc[mt][nt][1]);
                __half2 h1; h1.x = __float2half_rn(acc[mt][nt][2]); h1.y = __float2half_rn(acc[mt][nt][3]);
                *(__half2*)(C + (size_t)r0 * ldc + c0)       = h0;
                *(__half2*)(C + (size_t)(r0 + 8) * ldc + c0) = h1;
            } else {
                float* C = (float*)Cv;
                float2 v0 = {acc[mt][nt][0], acc[mt][nt][1]};
                float2 v1 = {acc[mt][nt][2], acc[mt][nt][3]};
                *(float2*)(C + (size_t)r0 * ldc + c0)       = v0;
                *(float2*)(C + (size_t)(r0 + 8) * ldc + c0) = v1;
            }
        }
    }

    if (OUT16) {
        if (blockIdx.x < 16) {
            float* ssbuf = (float*)smem;
            __syncthreads();
#pragma unroll
            for (int mt = 0; mt < 2; mt++) {
                float p0 = 0.0f, p1 = 0.0f;
#pragma unroll
                for (int nt = 0; nt < 8; nt++) {
                    p0 += acc[mt][nt][0]*acc[mt][nt][0] + acc[mt][nt][1]*acc[mt][nt][1];
                    p1 += acc[mt][nt][2]*acc[mt][nt][2] + acc[mt][nt][3]*acc[mt][nt][3];
                }
                p0 += __shfl_xor_sync(0xFFFFFFFFu, p0, 1);
                p0 += __shfl_xor_sync(0xFFFFFFFFu, p0, 2);
                p1 += __shfl_xor_sync(0xFFFFFFFFu, p1, 1);
                p1 += __shfl_xor_sync(0xFFFFFFFFu, p1, 2);
                if ((lane & 3) == 0) {
                    const int rloc = wm * 32 + mt * 16 + erow;
                    ssbuf[wn * 128 + rloc]     = p0;
                    ssbuf[wn * 128 + rloc + 8] = p1;
                }
            }
            __syncthreads();
            if (tid < 128) {
                float s = ssbuf[tid] + ssbuf[128 + tid];
                ssp[(size_t)(m0 + tid) * 16 + blockIdx.x] = s;
            }
        }
    }
}

// ---------------- combine ss partials -> rsqrt factors ----------------
__global__ __launch_bounds__(256)
void rsfact_kernel(const float* __restrict__ ssp, float* __restrict__ rsq,
                   float* __restrict__ rsk)
{
    const int idx = blockIdx.x * 256 + threadIdx.x;
    const int row = idx >> 1;
    const int slice = idx & 1;
    const float4* p = (const float4*)(ssp + (size_t)row * 16 + slice * 8);
    float4 a = p[0], b = p[1];
    float s = a.x + a.y + a.z + a.w + b.x + b.y + b.z + b.w;
    float rs = rsqrtf(s * (1.0f / DIM) + EPSV);
    (slice == 0 ? rsq : rsk)[row] = rs;
}

// ---------------- mma-based banded attention (ldmatrix.trans for V) ----------------
#define QROW 136
#define KROW 136
#define ASMEM (64*QROW*2 + 2*80*KROW*2 + 80*4)

__global__ __launch_bounds__(128, 3)
void attn_kernel(const __half* __restrict__ qkvh, const float* __restrict__ rsq,
                 const float* __restrict__ rsk, const float* __restrict__ qnw,
                 const float* __restrict__ knw, __half* __restrict__ yh)
{
    extern __shared__ char smraw[];
    __half* Qs = (__half*)smraw;             // 64 x 136
    __half* Ks = Qs + 64 * QROW;             // 80 x 136
    __half* Vs = Ks + 80 * KROW;             // 80 x 136 (raw, row-major)
    float*  rk = (float*)(Vs + 80 * KROW);   // 80
    const int tid  = threadIdx.x;
    const int lane = tid & 31;
    const int w    = tid >> 5;
    const int qb = blockIdx.x * 64;
    const int h  = blockIdx.y;
    const int b  = blockIdx.z;

    const __half* qbase = qkvh + (size_t)(b * SEQ) * NQKV + h * HD;
    const __half* kbase = qbase + DIM;
    const __half* vbase = qbase + 2 * DIM;

    if (tid < 80) {
        const int gr = qb - WIN + tid;
        rk[tid] = (gr >= 0) ? rsk[b * SEQ + tid + qb - WIN] : 0.0f;
    }
    // K + V staging (raw bits, zero-fill out-of-range)
    for (int idx = tid; idx < 80 * 16; idx += 128) {
        const int r = idx >> 4, c = idx & 15;
        const int gr = qb - WIN + r;
        uint4 uk = make_uint4(0u, 0u, 0u, 0u);
        uint4 uv = make_uint4(0u, 0u, 0u, 0u);
        if (gr >= 0) {
            uk = ((const uint4*)(kbase + (size_t)gr * NQKV))[c];
            uv = ((const uint4*)(vbase + (size_t)gr * NQKV))[c];
        }
        *(uint4*)(Ks + r * KROW + c * 8) = uk;
        *(uint4*)(Vs + r * KROW + c * 8) = uv;
    }
    // Q staging: fold rsq*scale*qnw*knw, round to fp16
    for (int idx = tid; idx < 64 * 16; idx += 128) {
        const int r = idx >> 4, c = idx & 15;
        const int t = qb + r;
        uint4 u = ((const uint4*)(qbase + (size_t)t * NQKV))[c];
        const float qf = rsq[b * SEQ + t] * 0.08838834764831845f;
        const float4 qw0 = ((const float4*)(qnw + h * HD + c * 8))[0];
        const float4 qw1 = ((const float4*)(qnw + h * HD + c * 8))[1];
        const float4 kw0 = ((const float4*)(knw + h * HD + c * 8))[0];
        const float4 kw1 = ((const float4*)(knw + h * HD + c * 8))[1];
        float f[8], g[8];
        const __half2* hp = (const __half2*)&u;
#pragma unroll
        for (int j = 0; j < 4; j++) {
            float2 t2 = __half22float2(hp[j]);
            f[2*j] = t2.x; f[2*j+1] = t2.y;
        }
        g[0]=qw0.x*kw0.x; g[1]=qw0.y*kw0.y; g[2]=qw0.z*kw0.z; g[3]=qw0.w*kw0.w;
        g[4]=qw1.x*kw1.x; g[5]=qw1.y*kw1.y; g[6]=qw1.z*kw1.z; g[7]=qw1.w*kw1.w;
        uint4 out;
        __half2* op = (__half2*)&out;
#pragma unroll
        for (int j = 0; j < 4; j++) {
            __half2 hh;
            hh.x = __float2half_rn(f[2*j]   * qf * g[2*j]);
            hh.y = __float2half_rn(f[2*j+1] * qf * g[2*j+1]);
            op[j] = hh;
        }
        *(uint4*)(Qs + r * QROW + c * 8) = out;
    }
    __syncthreads();

    const uint32_t Qb = smem_u32(Qs);
    const uint32_t Kb = smem_u32(Ks);
    const uint32_t Vb = smem_u32(Vs);
    const int r0 = w * 16;

    // ---- S = Q @ K^T : 16x32, 8 k-chunks ----
    float sc[4][4];
#pragma unroll
    for (int t4 = 0; t4 < 4; t4++)
#pragma unroll
        for (int q = 0; q < 4; q++) sc[t4][q] = 0.0f;

    const uint32_t aAddr = Qb + (uint32_t)(r0 + (lane & 15)) * (QROW*2) + (uint32_t)(lane >> 4) * 16;
    const int bc = (lane >> 3) & 1;
    const int brow_off = ((lane >> 4) << 3) + (lane & 7);
#pragma unroll
    for (int kc = 0; kc < 8; kc++) {
        uint32_t fA[4];
        ldm_x4(fA, aAddr + kc * 32);
#pragma unroll
        for (int pg = 0; pg < 2; pg++) {
            uint32_t fB[4];
            const int brow = r0 + pg * 16 + brow_off;
            ldm_x4(fB, Kb + (uint32_t)brow * (KROW*2) + (uint32_t)(kc * 2 + bc) * 16);
            mma_f16(sc[pg*2],     fA, &fB[0]);
            mma_f16(sc[pg*2 + 1], fA, &fB[2]);
        }
    }

    // ---- softmax in fragments ----
    const int crow = lane >> 2;
    const int ccol = (lane & 3) * 2;
    const float slope = exp2f(-(float)h);
    float mx0 = -1e30f, mx1 = -1e30f;
#pragma unroll
    for (int t4 = 0; t4 < 4; t4++) {
#pragma unroll
        for (int q = 0; q < 4; q++) {
            const int colL = t4 * 8 + ccol + (q & 1);
            const int rowL = crow + ((q & 2) ? 8 : 0);
            const int rel = colL - 16 - rowL;
            const bool valid = (rel <= 0) && (rel >= -WIN) && (qb + r0 + colL >= 16);
            float s = valid ? sc[t4][q] * rk[r0 + colL] + slope * (float)rel : -1e30f;
            sc[t4][q] = s;
            if (q & 2) mx1 = fmaxf(mx1, s); else mx0 = fmaxf(mx0, s);
        }
    }
    mx0 = fmaxf(mx0, __shfl_xor_sync(0xFFFFFFFFu, mx0, 1));
    mx0 = fmaxf(mx0, __shfl_xor_sync(0xFFFFFFFFu, mx0, 2));
    mx1 = fmaxf(mx1, __shfl_xor_sync(0xFFFFFFFFu, mx1, 1));
    mx1 = fmaxf(mx1, __shfl_xor_sync(0xFFFFFFFFu, mx1, 2));

    float l0 = 0.0f, l1 = 0.0f;
#pragma unroll
    for (int t4 = 0; t4 < 4; t4++) {
#pragma unroll
        for (int q = 0; q < 4; q++) {
            float e = __expf(sc[t4][q] - ((q & 2) ? mx1 : mx0));
            sc[t4][q] = e;
            if (q & 2) l1 += e; else l0 += e;
        }
    }
    l0 += __shfl_xor_sync(0xFFFFFFFFu, l0, 1);
    l0 += __shfl_xor_sync(0xFFFFFFFFu, l0, 2);
    l1 += __shfl_xor_sync(0xFFFFFFFFu, l1, 1);
    l1 += __shfl_xor_sync(0xFFFFFFFFu, l1, 2);
    const float inv0 = 1.0f / l0, inv1 = 1.0f / l1;

    // pack P into a-fragments
    uint32_t aP[2][4];
#pragma unroll
    for (int kc2 = 0; kc2 < 2; kc2++) {
        const int t0 = kc2 * 2, t1 = t0 + 1;
        __half2 h0, h1, h2v, h3;
        h0.x  = __float2half_rn(sc[t0][0] * inv0); h0.y  = __float2half_rn(sc[t0][1] * inv0);
        h1.x  = __float2half_rn(sc[t0][2] * inv1); h1.y  = __float2half_rn(sc[t0][3] * inv1);
        h2v.x = __float2half_rn(sc[t1][0] * inv0); h2v.y = __float2half_rn(sc[t1][1] * inv0);
        h3.x  = __float2half_rn(sc[t1][2] * inv1); h3.y  = __float2half_rn(sc[t1][3] * inv1);
        aP[kc2][0] = *(uint32_t*)&h0;
        aP[kc2][1] = *(uint32_t*)&h1;
        aP[kc2][2] = *(uint32_t*)&h2v;
        aP[kc2][3] = *(uint32_t*)&h3;
    }

    // ---- O = P @ V : 16x128, 2 k-chunks; B via ldmatrix.trans on row-major V ----
    float o[16][4];
#pragma unroll
    for (int nt = 0; nt < 16; nt++)
#pragma unroll
        for (int q = 0; q < 4; q++) o[nt][q] = 0.0f;

    const int vkrow = (lane & 15);          // key row within 16-chunk
    const int vcol8 = (lane >> 4) * 8;      // n sub-col
#pragma unroll
    for (int kc2 = 0; kc2 < 2; kc2++) {
        const uint32_t vrowAddr = Vb + (uint32_t)(r0 + kc2 * 16 + vkrow) * (KROW*2);
#pragma unroll
        for (int pg = 0; pg < 8; pg++) {
            uint32_t fB[4];
            ldm_x4_trans(fB, vrowAddr + (uint32_t)(pg * 16 + vcol8) * 2);
            mma_f16(o[pg*2],     aP[kc2], &fB[0]);
            mma_f16(o[pg*2 + 1], aP[kc2], &fB[2]);
        }
    }

    // ---- store y (fp16) ----
    __half* ybase = yh + (size_t)(b * SEQ + qb + r0) * DIM + h * HD;
#pragma unroll
    for (int nt = 0; nt < 16; nt++) {
        const int col = nt * 8 + ccol;
        __half2 h0; h0.x = __float2half_rn(o[nt][0]); h0.y = __float2half_rn(o[nt][1]);
        __half2 h1; h1.x = __float2half_rn(o[nt][2]); h1.y = __float2half_rn(o[nt][3]);
        *(__half2*)(ybase + (size_t)crow * DIM + col)       = h0;
        *(__half2*)(ybase + (size_t)(crow + 8) * DIM + col) = h1;
    }
}

// ---------------- launch ----------------
extern "C" void kernel_launch(void* const* d_in, const int* in_sizes, int n_in,
                              void* d_out, int out_size)
{
    const float* x   = (const float*)d_in[0];
    const float* wq  = (const float*)d_in[1];
    const float* wk  = (const float*)d_in[2];
    const float* wv  = (const float*)d_in[3];
    const float* wo  = (const float*)d_in[4];
    const float* qnw = (const float*)d_in[5];
    const float* knw = (const float*)d_in[6];
    float* out       = (float*)d_out;

    __half *wT, *xh, *qkvh, *yh;
    float *ssp, *rsq, *rsk;
    cudaGetSymbolAddress((void**)&wT,   g_wT);
    cudaGetSymbolAddress((void**)&xh,   g_xh);
    cudaGetSymbolAddress((void**)&qkvh, g_qkvh);
    cudaGetSymbolAddress((void**)&yh,   g_yh);
    cudaGetSymbolAddress((void**)&ssp,  g_ssp);
    cudaGetSymbolAddress((void**)&rsq,  g_rsq);
    cudaGetSymbolAddress((void**)&rsk,  g_rsk);

    cudaFuncSetAttribute(gemm_f16<0>, cudaFuncAttributeMaxDynamicSharedMemorySize, GSMEM);
    cudaFuncSetAttribute(gemm_f16<1>, cudaFuncAttributeMaxDynamicSharedMemorySize, GSMEM);
    cudaFuncSetAttribute(attn_kernel, cudaFuncAttributeMaxDynamicSharedMemorySize, ASMEM);

    // 1) prep
    dim3 pgrid(32, 32, 12), pblk(32, 8);
    prep_kernel<<<pgrid, pblk>>>(x, wq, wk, wv, wo, wT, xh);

    // 2) fused QKV projection -> fp16 + ss partials
    dim3 qkvgrid(NQKV/128, MR/128);
    gemm_f16<1><<<qkvgrid, 256, GSMEM>>>(xh, wT, qkvh, NQKV, ssp);

    // 3) rsqrt factors
    rsfact_kernel<<<MR*2/256, 256>>>(ssp, rsq, rsk);

    // 4) mma-based banded attention -> y fp16
    dim3 agrid(SEQ/64, NH, BATCH);
    attn_kernel<<<agrid, 128, ASMEM>>>(qkvh, rsq, rsk, qnw, knw, yh);

    // 5) output projection -> fp32 out
    dim3 ogrid(DIM/128, MR/128);
    gemm_f16<0><<<ogrid, 256, GSMEM>>>(yh, wT + (size_t)3072*DIM, out, DIM, nullptr);
}

// round 17
// speedup vs baseline: 1.4614x; 1.0285x over previous
#include <cuda_runtime.h>
#include <cuda_fp16.h>
#include <math.h>
#include <stdint.h>

// ---------------- problem constants ----------------
#define BATCH 4
#define SEQ   2048
#define DIM   1024
#define NH    8
#define HD    128
#define WIN   16
#define EPSV  1e-6f
#define MR    (BATCH*SEQ)   // 8192
#define NQKV  3072
#define NW    4096

// ---------------- device scratch ----------------
__device__ __align__(16) __half g_wT[NW*DIM];
__device__ __align__(16) __half g_xh[MR*DIM];
__device__ __align__(16) __half g_qkvh[MR*NQKV];
__device__ __align__(16) __half g_yh[MR*DIM];
__device__ __align__(16) float  g_ssp[MR*16];
__device__ __align__(16) float  g_rsq[MR];
__device__ __align__(16) float  g_rsk[MR];

// ---------------- PTX helpers ----------------
__device__ __forceinline__ uint32_t smem_u32(const void* p) {
    uint32_t a;
    asm("{ .reg .u64 t; cvta.to.shared.u64 t, %1; cvt.u32.u64 %0, t; }" : "=r"(a) : "l"(p));
    return a;
}
__device__ __forceinline__ void cp16(uint32_t d, const void* s) {
    asm volatile("cp.async.cg.shared.global [%0], [%1], 16;" :: "r"(d), "l"(s));
}
__device__ __forceinline__ void cp_commit() { asm volatile("cp.async.commit_group;" ::: "memory"); }
__device__ __forceinline__ void cp_wait2()  { asm volatile("cp.async.wait_group 2;" ::: "memory"); }
__device__ __forceinline__ void cp_wait1()  { asm volatile("cp.async.wait_group 1;" ::: "memory"); }
__device__ __forceinline__ void cp_wait0()  { asm volatile("cp.async.wait_group 0;" ::: "memory"); }

__device__ __forceinline__ void ldm_x4(uint32_t* r, uint32_t addr) {
    asm volatile("ldmatrix.sync.aligned.m8n8.x4.shared.b16 {%0,%1,%2,%3}, [%4];"
                 : "=r"(r[0]), "=r"(r[1]), "=r"(r[2]), "=r"(r[3]) : "r"(addr));
}
__device__ __forceinline__ void ldm_x4_trans(uint32_t* r, uint32_t addr) {
    asm volatile("ldmatrix.sync.aligned.m8n8.x4.trans.shared.b16 {%0,%1,%2,%3}, [%4];"
                 : "=r"(r[0]), "=r"(r[1]), "=r"(r[2]), "=r"(r[3]) : "r"(addr));
}
__device__ __forceinline__ void mma_f16(float* c, const uint32_t* a, const uint32_t* b) {
    asm volatile(
        "mma.sync.aligned.m16n8k16.row.col.f32.f16.f16.f32 "
        "{%0,%1,%2,%3}, {%4,%5,%6,%7}, {%8,%9}, {%0,%1,%2,%3};"
        : "+f"(c[0]), "+f"(c[1]), "+f"(c[2]), "+f"(c[3])
        : "r"(a[0]), "r"(a[1]), "r"(a[2]), "r"(a[3]), "r"(b[0]), "r"(b[1]));
}

// ---------------- prep: weights transpose->fp16 (z<4) + x convert (z>=4) ----------------
__global__ __launch_bounds__(256)
void prep_kernel(const float* __restrict__ x,
                 const float* __restrict__ wq, const float* __restrict__ wk,
                 const float* __restrict__ wv, const float* __restrict__ wo,
                 __half* __restrict__ wT, __half* __restrict__ xh)
{
    if (blockIdx.z < 4) {
        __shared__ float t[32][33];
        const float* W = (blockIdx.z == 0) ? wq : (blockIdx.z == 1) ? wk
                        : (blockIdx.z == 2) ? wv : wo;
        __half* out = wT + (size_t)blockIdx.z * DIM * DIM;
        const int c0 = blockIdx.x * 32, r0 = blockIdx.y * 32;
        const int tx = threadIdx.x, ty = threadIdx.y;
#pragma unroll
        for (int j = 0; j < 4; j++)
            t[ty + 8*j][tx] = W[(size_t)(r0 + ty + 8*j) * DIM + c0 + tx];
        __syncthreads();
#pragma unroll
        for (int j = 0; j < 4; j++)
            out[(size_t)(c0 + ty + 8*j) * DIM + (r0 + tx)] = __float2half_rn(t[tx][ty + 8*j]);
    } else {
        const int tid = threadIdx.y * 32 + threadIdx.x;
        const int blocklin = (blockIdx.z - 4) * 1024 + blockIdx.y * 32 + blockIdx.x;
        const int i = blocklin * 256 + tid;
        float4 v = ((const float4*)x)[i];
        __half2 H0; H0.x = __float2half_rn(v.x); H0.y = __float2half_rn(v.y);
        __half2 H1; H1.x = __float2half_rn(v.z); H1.y = __float2half_rn(v.w);
        ((__half2*)xh)[2*i]   = H0;
        ((__half2*)xh)[2*i+1] = H1;
    }
}

// ---------------- fp16 warp-MMA GEMM (R9 config, ss-fused epilogue) ----------------
#define TILEB  8192
#define STAGEB (2*TILEB)
#define GSMEM  (4*STAGEB)

__device__ __forceinline__ uint32_t swz_addr(uint32_t tile, int row, int chunk) {
    return tile + row * 64 + (((uint32_t)(chunk ^ ((row >> 1) & 3))) << 4);
}
__device__ __forceinline__ void ld_tile(uint32_t sdst, const __half* g,
                                        int grow0, int k0, int lrow, int lc0)
{
    const __half* src = g + (size_t)(grow0 + lrow) * DIM + k0 + lc0 * 8;
    cp16(swz_addr(sdst, lrow, lc0),     src);
    cp16(swz_addr(sdst, lrow, lc0 + 1), src + 8);
}

template<int OUT16>
__global__ __launch_bounds__(256, 2)
void gemm_f16(const __half* __restrict__ a, const __half* __restrict__ b,
              void* __restrict__ Cv, int ldc, float* __restrict__ ssp)
{
    extern __shared__ char smem[];
    const uint32_t sbase = smem_u32(smem);
    const int tid  = threadIdx.x;
    const int lane = tid & 31;
    const int wid  = tid >> 5;
    const int wm   = wid >> 1;
    const int wn   = wid & 1;
    const int m0 = blockIdx.y * 128;
    const int n0 = blockIdx.x * 128;

    const int lrow = tid >> 1;
    const int lc0  = (tid & 1) * 2;

    int arow[2], browx[4];
#pragma unroll
    for (int mt = 0; mt < 2; mt++) arow[mt] = wm * 32 + mt * 16 + (lane & 15);
#pragma unroll
    for (int p = 0; p < 4; p++)
        browx[p] = wn * 64 + p * 16 + ((lane >> 4) << 3) + (lane & 7);
    const int ac = lane >> 4;
    const int bc = (lane >> 3) & 1;

    float acc[2][8][4];
#pragma unroll
    for (int mt = 0; mt < 2; mt++)
#pragma unroll
        for (int nt = 0; nt < 8; nt++)
#pragma unroll
            for (int q = 0; q < 4; q++) acc[mt][nt][q] = 0.0f;

#pragma unroll
    for (int s = 0; s < 3; s++) {
        const uint32_t st = sbase + s * STAGEB;
        const int k0 = s * 32;
        ld_tile(st,         a, m0, k0, lrow, lc0);
        ld_tile(st + TILEB, b, n0, k0, lrow, lc0);
        cp_commit();
    }

    const int NIT = DIM / 32;
    for (int i = 0; i < NIT; i++) {
        if (i < NIT - 2)      cp_wait2();
        else if (i == NIT-2)  cp_wait1();
        else                  cp_wait0();
        __syncthreads();

        if (i + 3 < NIT) {
            const uint32_t st = sbase + ((i + 3) & 3) * STAGEB;
            const int k0 = (i + 3) * 32;
            ld_tile(st,         a, m0, k0, lrow, lc0);
            ld_tile(st + TILEB, b, n0, k0, lrow, lc0);
            cp_commit();
        }

        const uint32_t st = sbase + (i & 3) * STAGEB;
        const uint32_t sA = st;
        const uint32_t sB = st + TILEB;

#pragma unroll
        for (int kh = 0; kh < 2; kh++) {
            uint32_t fB[4][4], fA[2][4];
#pragma unroll
            for (int p = 0; p < 4; p++)
                ldm_x4(fB[p], swz_addr(sB, browx[p], kh * 2 + bc));
#pragma unroll
            for (int mt = 0; mt < 2; mt++)
                ldm_x4(fA[mt], swz_addr(sA, arow[mt], kh * 2 + ac));
#pragma unroll
            for (int mt = 0; mt < 2; mt++)
#pragma unroll
                for (int p = 0; p < 4; p++) {
                    mma_f16(acc[mt][p*2],     fA[mt], &fB[p][0]);
                    mma_f16(acc[mt][p*2 + 1], fA[mt], &fB[p][2]);
                }
        }
    }

    const int erow = lane >> 2;
    const int ecol = (lane & 3) * 2;
#pragma unroll
    for (int mt = 0; mt < 2; mt++) {
#pragma unroll
        for (int nt = 0; nt < 8; nt++) {
            const int r0 = m0 + wm * 32 + mt * 16 + erow;
            const int c0 = n0 + wn * 64 + nt * 8 + ecol;
            if (OUT16) {
                __half* C = (__half*)Cv;
                __half2 h0; h0.x = __float2half_rn(acc[mt][nt][0]); h0.y = __float2half_rn(acc[mt][nt][1]);
                __half2 h1; h1.x = __float2half_rn(acc[mt][nt][2]); h1.y = __float2half_rn(acc[mt][nt][3]);
                *(__half2*)(C + (size_t)r0 * ldc + c0)       = h0;
                *(__half2*)(C + (size_t)(r0 + 8) * ldc + c0) = h1;
            } else {
                float* C = (float*)Cv;
                float2 v0 = {acc[mt][nt][0], acc[mt][nt][1]};
                float2 v1 = {acc[mt][nt][2], acc[mt][nt][3]};
                *(float2*)(C + (size_t)r0 * ldc + c0)       = v0;
                *(float2*)(C + (size_t)(r0 + 8) * ldc + c0) = v1;
            }
        }
    }

    if (OUT16) {
        if (blockIdx.x < 16) {
            float* ssbuf = (float*)smem;
            __syncthreads();
#pragma unroll
            for (int mt = 0; mt < 2; mt++) {
                float p0 = 0.0f, p1 = 0.0f;
#pragma unroll
                for (int nt = 0; nt < 8; nt++) {
                    p0 += acc[mt][nt][0]*acc[mt][nt][0] + acc[mt][nt][1]*acc[mt][nt][1];
                    p1 += acc[mt][nt][2]*acc[mt][nt][2] + acc[mt][nt][3]*acc[mt][nt][3];
                }
                p0 += __shfl_xor_sync(0xFFFFFFFFu, p0, 1);
                p0 += __shfl_xor_sync(0xFFFFFFFFu, p0, 2);
                p1 += __shfl_xor_sync(0xFFFFFFFFu, p1, 1);
                p1 += __shfl_xor_sync(0xFFFFFFFFu, p1, 2);
                if ((lane & 3) == 0) {
                    const int rloc = wm * 32 + mt * 16 + erow;
                    ssbuf[wn * 128 + rloc]     = p0;
                    ssbuf[wn * 128 + rloc + 8] = p1;
                }
            }
            __syncthreads();
            if (tid < 128) {
                float s = ssbuf[tid] + ssbuf[128 + tid];
                ssp[(size_t)(m0 + tid) * 16 + blockIdx.x] = s;
            }
        }
    }
}

// ---------------- combine ss partials -> rsqrt factors ----------------
__global__ __launch_bounds__(256)
void rsfact_kernel(const float* __restrict__ ssp, float* __restrict__ rsq,
                   float* __restrict__ rsk)
{
    const int idx = blockIdx.x * 256 + threadIdx.x;
    const int row = idx >> 1;
    const int slice = idx & 1;
    const float4* p = (const float4*)(ssp + (size_t)row * 16 + slice * 8);
    float4 a = p[0], b = p[1];
    float s = a.x + a.y + a.z + a.w + b.x + b.y + b.z + b.w;
    float rs = rsqrtf(s * (1.0f / DIM) + EPSV);
    (slice == 0 ? rsq : rsk)[row] = rs;
}

// ---------------- mma-based banded attention v3 ----------------
// block = 128 queries x (h, b); 256 threads (8 warps, 16 queries each).
// K/V window: 144 rows staged raw fp16; Q fragments built directly from global.
#define NR   144
#define KROW 136
#define ASMEM (2*NR*KROW*2 + NR*4)

__global__ __launch_bounds__(256, 2)
void attn_kernel(const __half* __restrict__ qkvh, const float* __restrict__ rsq,
                 const float* __restrict__ rsk, const float* __restrict__ qnw,
                 const float* __restrict__ knw, __half* __restrict__ yh)
{
    extern __shared__ char smraw[];
    __half* Ks = (__half*)smraw;             // 144 x 136
    __half* Vs = Ks + NR * KROW;             // 144 x 136
    float*  rk = (float*)(Vs + NR * KROW);   // 144
    const int tid  = threadIdx.x;
    const int lane = tid & 31;
    const int w    = tid >> 5;               // 0..7
    const int qb = blockIdx.x * 128;
    const int h  = blockIdx.y;
    const int b  = blockIdx.z;

    const __half* qbase = qkvh + (size_t)(b * SEQ) * NQKV + h * HD;
    const __half* kbase = qbase + DIM;
    const __half* vbase = qbase + 2 * DIM;

    if (tid < NR) {
        const int gr = qb - WIN + tid;
        rk[tid] = (gr >= 0) ? rsk[b * SEQ + gr] : 0.0f;
    }
    for (int idx = tid; idx < NR * 16; idx += 256) {
        const int r = idx >> 4, c = idx & 15;
        const int gr = qb - WIN + r;
        uint4 uk = make_uint4(0u, 0u, 0u, 0u);
        uint4 uv = make_uint4(0u, 0u, 0u, 0u);
        if (gr >= 0) {
            uk = ((const uint4*)(kbase + (size_t)gr * NQKV))[c];
            uv = ((const uint4*)(vbase + (size_t)gr * NQKV))[c];
        }
        *(uint4*)(Ks + r * KROW + c * 8) = uk;
        *(uint4*)(Vs + r * KROW + c * 8) = uv;
    }
    __syncthreads();

    const uint32_t Kb = smem_u32(Ks);
    const uint32_t Vb = smem_u32(Vs);
    const int r0 = w * 16;
    const int crow = lane >> 2;
    const int ccol = (lane & 3) * 2;
    const int t0 = qb + r0 + crow;
    const int t1 = t0 + 8;
    const float qf0 = rsq[b * SEQ + t0] * 0.08838834764831845f;
    const float qf1 = rsq[b * SEQ + t1] * 0.08838834764831845f;

    // ---- S = Q @ K^T : 16x32, Q fragments built from global ----
    float sc[4][4];
#pragma unroll
    for (int t4 = 0; t4 < 4; t4++)
#pragma unroll
        for (int q = 0; q < 4; q++) sc[t4][q] = 0.0f;

    const int bc = (lane >> 3) & 1;
    const int brow_off = ((lane >> 4) << 3) + (lane & 7);
#pragma unroll
    for (int kc = 0; kc < 8; kc++) {
        // build a-fragment: a0=(crow,ccol) a1=(crow+8,ccol) a2=(crow,ccol+8) a3=(crow+8,ccol+8)
        uint32_t fA[4];
        {
            const int col = kc * 16 + ccol;
            const float2 qw0 = *(const float2*)(qnw + h * HD + col);
            const float2 kw0 = *(const float2*)(knw + h * HD + col);
            const float2 qw1 = *(const float2*)(qnw + h * HD + col + 8);
            const float2 kw1 = *(const float2*)(knw + h * HD + col + 8);
            const float g0x = qw0.x * kw0.x, g0y = qw0.y * kw0.y;
            const float g1x = qw1.x * kw1.x, g1y = qw1.y * kw1.y;
            float2 f0 = __half22float2(*(const __half2*)(qbase + (size_t)t0 * NQKV + col));
            float2 f1 = __half22float2(*(const __half2*)(qbase + (size_t)t1 * NQKV + col));
            float2 f2 = __half22float2(*(const __half2*)(qbase + (size_t)t0 * NQKV + col + 8));
            float2 f3 = __half22float2(*(const __half2*)(qbase + (size_t)t1 * NQKV + col + 8));
            __half2 a0, a1, a2, a3;
            a0.x = __float2half_rn(f0.x * qf0 * g0x); a0.y = __float2half_rn(f0.y * qf0 * g0y);
            a1.x = __float2half_rn(f1.x * qf1 * g0x); a1.y = __float2half_rn(f1.y * qf1 * g0y);
            a2.x = __float2half_rn(f2.x * qf0 * g1x); a2.y = __float2half_rn(f2.y * qf0 * g1y);
            a3.x = __float2half_rn(f3.x * qf1 * g1x); a3.y = __float2half_rn(f3.y * qf1 * g1y);
            fA[0] = *(uint32_t*)&a0; fA[1] = *(uint32_t*)&a1;
            fA[2] = *(uint32_t*)&a2; fA[3] = *(uint32_t*)&a3;
        }
#pragma unroll
        for (int pg = 0; pg < 2; pg++) {
            uint32_t fB[4];
            const int brow = r0 + pg * 16 + brow_off;
            ldm_x4(fB, Kb + (uint32_t)brow * (KROW*2) + (uint32_t)(kc * 2 + bc) * 16);
            mma_f16(sc[pg*2],     fA, &fB[0]);
            mma_f16(sc[pg*2 + 1], fA, &fB[2]);
        }
    }

    // ---- softmax in fragments ----
    const float slope = exp2f(-(float)h);
    float mx0 = -1e30f, mx1 = -1e30f;
#pragma unroll
    for (int t4 = 0; t4 < 4; t4++) {
#pragma unroll
        for (int q = 0; q < 4; q++) {
            const int colL = t4 * 8 + ccol + (q & 1);
            const int rowL = crow + ((q & 2) ? 8 : 0);
            const int rel = colL - 16 - rowL;
            const bool valid = (rel <= 0) && (rel >= -WIN) && (qb + r0 + colL >= 16);
            float s = valid ? sc[t4][q] * rk[r0 + colL] + slope * (float)rel : -1e30f;
            sc[t4][q] = s;
            if (q & 2) mx1 = fmaxf(mx1, s); else mx0 = fmaxf(mx0, s);
        }
    }
    mx0 = fmaxf(mx0, __shfl_xor_sync(0xFFFFFFFFu, mx0, 1));
    mx0 = fmaxf(mx0, __shfl_xor_sync(0xFFFFFFFFu, mx0, 2));
    mx1 = fmaxf(mx1, __shfl_xor_sync(0xFFFFFFFFu, mx1, 1));
    mx1 = fmaxf(mx1, __shfl_xor_sync(0xFFFFFFFFu, mx1, 2));

    float l0 = 0.0f, l1 = 0.0f;
#pragma unroll
    for (int t4 = 0; t4 < 4; t4++) {
#pragma unroll
        for (int q = 0; q < 4; q++) {
            float e = __expf(sc[t4][q] - ((q & 2) ? mx1 : mx0));
            sc[t4][q] = e;
            if (q & 2) l1 += e; else l0 += e;
        }
    }
    l0 += __shfl_xor_sync(0xFFFFFFFFu, l0, 1);
    l0 += __shfl_xor_sync(0xFFFFFFFFu, l0, 2);
    l1 += __shfl_xor_sync(0xFFFFFFFFu, l1, 1);
    l1 += __shfl_xor_sync(0xFFFFFFFFu, l1, 2);
    const float inv0 = 1.0f / l0, inv1 = 1.0f / l1;

    // pack P into a-fragments
    uint32_t aP[2][4];
#pragma unroll
    for (int kc2 = 0; kc2 < 2; kc2++) {
        const int tA = kc2 * 2, tB = tA + 1;
        __half2 h0, h1, h2v, h3;
        h0.x  = __float2half_rn(sc[tA][0] * inv0); h0.y  = __float2half_rn(sc[tA][1] * inv0);
        h1.x  = __float2half_rn(sc[tA][2] * inv1); h1.y  = __float2half_rn(sc[tA][3] * inv1);
        h2v.x = __float2half_rn(sc[tB][0] * inv0); h2v.y = __float2half_rn(sc[tB][1] * inv0);
        h3.x  = __float2half_rn(sc[tB][2] * inv1); h3.y  = __float2half_rn(sc[tB][3] * inv1);
        aP[kc2][0] = *(uint32_t*)&h0;
        aP[kc2][1] = *(uint32_t*)&h1;
        aP[kc2][2] = *(uint32_t*)&h2v;
        aP[kc2][3] = *(uint32_t*)&h3;
    }

    // ---- O = P @ V : 16x128; B via ldmatrix.trans on row-major V ----
    float o[16][4];
#pragma unroll
    for (int nt = 0; nt < 16; nt++)
#pragma unroll
        for (int q = 0; q < 4; q++) o[nt][q] = 0.0f;

    const int vkrow = (lane & 15);
    const int vcol8 = (lane >> 4) * 8;
#pragma unroll
    for (int kc2 = 0; kc2 < 2; kc2++) {
        const uint32_t vrowAddr = Vb + (uint32_t)(r0 + kc2 * 16 + vkrow) * (KROW*2);
#pragma unroll
        for (int pg = 0; pg < 8; pg++) {
            uint32_t fB[4];
            ldm_x4_trans(fB, vrowAddr + (uint32_t)(pg * 16 + vcol8) * 2);
            mma_f16(o[pg*2],     aP[kc2], &fB[0]);
            mma_f16(o[pg*2 + 1], aP[kc2], &fB[2]);
        }
    }

    // ---- store y (fp16) ----
    __half* ybase = yh + (size_t)(b * SEQ + qb + r0) * DIM + h * HD;
#pragma unroll
    for (int nt = 0; nt < 16; nt++) {
        const int col = nt * 8 + ccol;
        __half2 h0; h0.x = __float2half_rn(o[nt][0]); h0.y = __float2half_rn(o[nt][1]);
        __half2 h1; h1.x = __float2half_rn(o[nt][2]); h1.y = __float2half_rn(o[nt][3]);
        *(__half2*)(ybase + (size_t)crow * DIM + col)       = h0;
        *(__half2*)(ybase + (size_t)(crow + 8) * DIM + col) = h1;
    }
}

// ---------------- launch ----------------
extern "C" void kernel_launch(void* const* d_in, const int* in_sizes, int n_in,
                              void* d_out, int out_size)
{
    const float* x   = (const float*)d_in[0];
    const float* wq  = (const float*)d_in[1];
    const float* wk  = (const float*)d_in[2];
    const float* wv  = (const float*)d_in[3];
    const float* wo  = (const float*)d_in[4];
    const float* qnw = (const float*)d_in[5];
    const float* knw = (const float*)d_in[6];
    float* out       = (float*)d_out;

    __half *wT, *xh, *qkvh, *yh;
    float *ssp, *rsq, *rsk;
    cudaGetSymbolAddress((void**)&wT,   g_wT);
    cudaGetSymbolAddress((void**)&xh,   g_xh);
    cudaGetSymbolAddress((void**)&qkvh, g_qkvh);
    cudaGetSymbolAddress((void**)&yh,   g_yh);
    cudaGetSymbolAddress((void**)&ssp,  g_ssp);
    cudaGetSymbolAddress((void**)&rsq,  g_rsq);
    cudaGetSymbolAddress((void**)&rsk,  g_rsk);

    cudaFuncSetAttribute(gemm_f16<0>, cudaFuncAttributeMaxDynamicSharedMemorySize, GSMEM);
    cudaFuncSetAttribute(gemm_f16<1>, cudaFuncAttributeMaxDynamicSharedMemorySize, GSMEM);
    cudaFuncSetAttribute(attn_kernel, cudaFuncAttributeMaxDynamicSharedMemorySize, ASMEM);

    // 1) prep
    dim3 pgrid(32, 32, 12), pblk(32, 8);
    prep_kernel<<<pgrid, pblk>>>(x, wq, wk, wv, wo, wT, xh);

    // 2) fused QKV projection -> fp16 + ss partials
    dim3 qkvgrid(NQKV/128, MR/128);
    gemm_f16<1><<<qkvgrid, 256, GSMEM>>>(xh, wT, qkvh, NQKV, ssp);

    // 3) rsqrt factors
    rsfact_kernel<<<MR*2/256, 256>>>(ssp, rsq, rsk);

    // 4) mma-based banded attention -> y fp16
    dim3 agrid(SEQ/128, NH, BATCH);
    attn_kernel<<<agrid, 256, ASMEM>>>(qkvh, rsq, rsk, qnw, knw, yh);

    // 5) output projection -> fp32 out
    dim3 ogrid(DIM/128, MR/128);
    gemm_f16<0><<<ogrid, 256, GSMEM>>>(yh, wT + (size_t)3072*DIM, out, DIM, nullptr);
}